// round 12
// baseline (speedup 1.0000x reference)
#include <cuda_runtime.h>
#include <cuda_bf16.h>
#include <cstdint>
#include <cstddef>

#define EPS_BN 1e-5f

constexpr int Bb = 4;
constexpr int Cc = 2048;
constexpr int Rr = 512;
constexpr int Nn = 4096;   // H*W

constexpr size_t NC = (size_t)Bb * Nn * Cc;
constexpr size_t NR = (size_t)Bb * Nn * Rr;
constexpr size_t NNe = (size_t)Bb * Nn * Nn;

constexpr size_t WOF[5] = {0, 1048576, 1310720, 1572864, 1835008};
constexpr size_t WTOT = 2883584;

// ---- scratch (allocation-free) ----
__device__ __nv_bfloat16 g_XTh[NC], g_XTl[NC];
__device__ __nv_bfloat16 g_FTh[NR], g_FTl[NR];
__device__ float         g_FTf[NR];
__device__ __nv_bfloat16 g_QTh[NR], g_QTl[NR];
__device__ __nv_bfloat16 g_KTh[NR], g_KTl[NR];
__device__ float         g_Vf[NR];                      // [B][R][N] fp32
__device__ int8_t        g_Vd1[NR], g_Vd0[NR];
__device__ float         g_sV[(size_t)Bb * Rr];
__device__ float         g_S[NNe];
__device__ int8_t        g_Pd1[NNe], g_Pd0[NNe];        // [B][N][N]
__device__ float         g_sP[(size_t)Bb * Nn];
__device__ float         g_UT[NR];
__device__ __nv_bfloat16 g_WTh[NR], g_WTl[NR];
__device__ __nv_bfloat16 g_Wph[WTOT], g_Wpl[WTOT];
__device__ float g_alpha[5 * 2048], g_beta[5 * 2048];

// ===================== helpers =====================
__device__ __forceinline__ uint32_t smem_u32(const void* p) {
    uint32_t a;
    asm("{ .reg .u64 t; cvta.to.shared.u64 t, %1; cvt.u32.u64 %0, t; }" : "=r"(a) : "l"(p));
    return a;
}
__device__ __forceinline__ void ldsm4(uint32_t* r, uint32_t addr) {
    asm volatile("ldmatrix.sync.aligned.m8n8.x4.shared.b16 {%0,%1,%2,%3}, [%4];"
                 : "=r"(r[0]), "=r"(r[1]), "=r"(r[2]), "=r"(r[3]) : "r"(addr));
}
__device__ __forceinline__ void mma_bf16(float* c, const uint32_t* a, uint32_t b0, uint32_t b1) {
    asm volatile(
        "mma.sync.aligned.m16n8k16.row.col.f32.bf16.bf16.f32 "
        "{%0,%1,%2,%3}, {%4,%5,%6,%7}, {%8,%9}, {%0,%1,%2,%3};"
        : "+f"(c[0]), "+f"(c[1]), "+f"(c[2]), "+f"(c[3])
        : "r"(a[0]), "r"(a[1]), "r"(a[2]), "r"(a[3]), "r"(b0), "r"(b1));
}
__device__ __forceinline__ void mma_s8(int* c, const uint32_t* a, uint32_t b0, uint32_t b1) {
    asm volatile(
        "mma.sync.aligned.m16n8k32.row.col.s32.s8.s8.s32 "
        "{%0,%1,%2,%3}, {%4,%5,%6,%7}, {%8,%9}, {%0,%1,%2,%3};"
        : "+r"(c[0]), "+r"(c[1]), "+r"(c[2]), "+r"(c[3])
        : "r"(a[0]), "r"(a[1]), "r"(a[2]), "r"(a[3]), "r"(b0), "r"(b1));
}
__device__ __forceinline__ void cp16(uint32_t s, const void* g) {
    asm volatile("cp.async.cg.shared.global [%0], [%1], 16;" :: "r"(s), "l"(g));
}
__device__ __forceinline__ void cp_commit() {
    asm volatile("cp.async.commit_group;" ::: "memory");
}
__device__ __forceinline__ void cp_wait0() {
    asm volatile("cp.async.wait_group 0;" ::: "memory");
}
__device__ __forceinline__ void split1(float x, __nv_bfloat16& h, __nv_bfloat16& l) {
    h = __float2bfloat16_rn(x);
    l = __float2bfloat16_rn(x - __bfloat162float(h));
}
__device__ __forceinline__ uint32_t pack2(__nv_bfloat16 a, __nv_bfloat16 b) {
    __nv_bfloat162 p; p.x = a; p.y = b;
    return *reinterpret_cast<uint32_t*>(&p);
}
// int15 -> two int8 digits: v = 128*d1 + d0, |d0|<=64
__device__ __forceinline__ void digits(int v, int8_t& d1, int8_t& d0) {
    int q = __float2int_rn((float)v * 0.0078125f);
    d1 = (int8_t)q;
    d0 = (int8_t)(v - q * 128);
}

// ===================== prep =====================
struct PrepArgs {
    const float* W[5];
    const float* g[5];
    const float* b[5];
    const float* m[5];
    const float* v[5];
};

__global__ void prep_kernel(PrepArgs a) {
    const size_t wof[5] = {0, 1048576, 1310720, 1572864, 1835008};
    const int wsz[5] = {1048576, 262144, 262144, 262144, 1048576};
    int id = blockIdx.x * blockDim.x + threadIdx.x;
    if (id < 4096) {
        int L, i;
        if (id < 2048) { L = id >> 9; i = id & 511; }
        else { L = 4; i = id - 2048; }
        float al = a.g[L][i] * rsqrtf(a.v[L][i] + EPS_BN);
        g_alpha[L * 2048 + i] = al;
        g_beta[L * 2048 + i] = a.b[L][i] - a.m[L][i] * al;
        return;
    }
    size_t w = (size_t)id - 4096;
    if (w >= WTOT) return;
    int L = 0;
    size_t off = w;
    while (L < 4 && off >= (size_t)wsz[L]) { off -= wsz[L]; ++L; }
    float x = a.W[L][off];
    split1(x, g_Wph[wof[L] + off], g_Wpl[wof[L] + off]);
}

// ===================== feature transpose + split ============================
__global__ __launch_bounds__(256) void xt_kernel(const float* __restrict__ X) {
    __shared__ float s[32][33];
    const int c0 = blockIdx.x * 32;
    const int n0 = blockIdx.y * 32;
    const size_t zo = (size_t)blockIdx.z * Cc * Nn;
    const int tx = threadIdx.x & 31;
    const int ty = threadIdx.x >> 5;
#pragma unroll
    for (int i = 0; i < 4; ++i)
        s[ty + 8 * i][tx] = X[zo + (size_t)(c0 + ty + 8 * i) * Nn + n0 + tx];
    __syncthreads();
    const size_t zo2 = (size_t)blockIdx.z * Nn * Cc;
#pragma unroll
    for (int i = 0; i < 4; ++i) {
        float val = s[tx][ty + 8 * i];
        size_t o = zo2 + (size_t)(n0 + ty + 8 * i) * Cc + c0 + tx;
        split1(val, g_XTh[o], g_XTl[o]);
    }
}

// ===================== canonical split-bf16 GEMM (R8 form) ==================
// C[i,j] = sum_k A[i,k]*B[j,k];  A planes [M][K], B planes [N][K] (K contig).
// SCALE: 0 none, 1 row alpha[i], 2 col alpha[j]; >0 implies ReLU.
// Block tile 128x128xBK32, 128 threads (4 warps 2x2, warp tile 64x64).
template <int SCALE, bool OF32, bool OPL, bool WLO>
__global__ __launch_bounds__(128, 2) void gemm_bf16s(
    const __nv_bfloat16* __restrict__ Ah, const __nv_bfloat16* __restrict__ Al,
    const __nv_bfloat16* __restrict__ Bh, const __nv_bfloat16* __restrict__ Bl,
    float* __restrict__ Cf, __nv_bfloat16* __restrict__ Ch, __nv_bfloat16* __restrict__ Cl,
    int K, int ldc, long sA, long sB, long sC,
    const float* __restrict__ alpha, const float* __restrict__ beta) {
    extern __shared__ __align__(16) char smem[];
    const uint32_t su = smem_u32(smem);

    constexpr int STGB = 40960;
    constexpr int BOFF = 20480;

    const int t = threadIdx.x;
    const int lane = t & 31;
    const int wid = t >> 5;
    const int warp_m = wid >> 1;
    const int warp_n = wid & 1;
    const int bi = blockIdx.y * 128;
    const int bj = blockIdx.x * 128;
    const size_t zA = (size_t)sA * blockIdx.z;
    const size_t zB = (size_t)sB * blockIdx.z;
    const size_t zC = (size_t)sC * blockIdx.z;

    const int row = t >> 2;
    const int kc = t & 3;

    auto load_stage = [&](int stage, int k0) {
        const uint32_t sb = su + stage * STGB;
#pragma unroll
        for (int i = 0; i < 4; ++i) {
            int r = row + 32 * i;
            uint32_t so = r * 80 + kc * 16;
            cp16(sb + so,         (const char*)(Ah + zA + (size_t)(bi + r) * K + k0) + kc * 16);
            cp16(sb + 10240 + so, (const char*)(Al + zA + (size_t)(bi + r) * K + k0) + kc * 16);
            cp16(sb + BOFF + so,  (const char*)(Bh + zB + (size_t)(bj + r) * K + k0) + kc * 16);
            cp16(sb + 30720 + so, (const char*)(Bl + zB + (size_t)(bj + r) * K + k0) + kc * 16);
        }
        cp_commit();
    };

    float acc[4][8][4] = {};
    const int T = K / 32;

    load_stage(0, 0);

    const uint32_t aoff = (uint32_t)((warp_m * 64 + (lane & 15)) * 80 + (lane >> 4) * 16);
    const uint32_t boff = (uint32_t)(BOFF + (warp_n * 64 + (lane & 15)) * 80 + (lane >> 4) * 16);

    for (int tt = 0; tt < T; ++tt) {
        cp_wait0();
        __syncthreads();
        if (tt + 1 < T) load_stage((tt + 1) & 1, (tt + 1) * 32);

        const uint32_t sb = su + (tt & 1) * STGB;
        const uint32_t aHi = sb + aoff, aLo = aHi + 10240;
        const uint32_t bHi = sb + boff, bLo = bHi + 10240;

#pragma unroll
        for (int ks = 0; ks < 2; ++ks) {
            const uint32_t kof = (uint32_t)(ks * 32);
            uint32_t bh[4][4], bl[4][4];
#pragma unroll
            for (int np = 0; np < 4; ++np) {
                ldsm4(bh[np], bHi + (uint32_t)(np * 16 * 80) + kof);
                ldsm4(bl[np], bLo + (uint32_t)(np * 16 * 80) + kof);
            }
#pragma unroll
            for (int mt = 0; mt < 4; ++mt) {
                uint32_t ah[4], al_[4];
                ldsm4(ah, aHi + (uint32_t)(mt * 16 * 80) + kof);
                ldsm4(al_, aLo + (uint32_t)(mt * 16 * 80) + kof);
#pragma unroll
                for (int nt = 0; nt < 8; ++nt) {
                    const uint32_t* h = bh[nt >> 1];
                    const uint32_t* l = bl[nt >> 1];
                    mma_bf16(acc[mt][nt], ah, h[nt & 1], h[2 + (nt & 1)]);
                    mma_bf16(acc[mt][nt], al_, h[nt & 1], h[2 + (nt & 1)]);
                    mma_bf16(acc[mt][nt], ah, l[nt & 1], l[2 + (nt & 1)]);
                }
            }
        }
    }

#pragma unroll
    for (int mt = 0; mt < 4; ++mt) {
        const int m0 = bi + warp_m * 64 + mt * 16 + (lane >> 2);
        float ra0 = 1.f, rb0 = 0.f, ra1 = 1.f, rb1 = 0.f;
        if (SCALE == 1) {
            ra0 = alpha[m0]; rb0 = beta[m0];
            ra1 = alpha[m0 + 8]; rb1 = beta[m0 + 8];
        }
#pragma unroll
        for (int nt = 0; nt < 8; ++nt) {
            const int n = bj + warp_n * 64 + nt * 8 + (lane & 3) * 2;
            float v0 = acc[mt][nt][0], v1 = acc[mt][nt][1];
            float v2 = acc[mt][nt][2], v3 = acc[mt][nt][3];
            if (SCALE == 1) {
                v0 = fmaxf(fmaf(ra0, v0, rb0), 0.f); v1 = fmaxf(fmaf(ra0, v1, rb0), 0.f);
                v2 = fmaxf(fmaf(ra1, v2, rb1), 0.f); v3 = fmaxf(fmaf(ra1, v3, rb1), 0.f);
            } else if (SCALE == 2) {
                float ca0 = alpha[n], cb0 = beta[n], ca1 = alpha[n + 1], cb1 = beta[n + 1];
                v0 = fmaxf(fmaf(ca0, v0, cb0), 0.f); v1 = fmaxf(fmaf(ca1, v1, cb1), 0.f);
                v2 = fmaxf(fmaf(ca0, v2, cb0), 0.f); v3 = fmaxf(fmaf(ca1, v3, cb1), 0.f);
            }
            if (OF32) {
                *reinterpret_cast<float2*>(&Cf[zC + (size_t)m0 * ldc + n]) = make_float2(v0, v1);
                *reinterpret_cast<float2*>(&Cf[zC + (size_t)(m0 + 8) * ldc + n]) = make_float2(v2, v3);
            }
            if (OPL) {
                __nv_bfloat16 h0, l0, h1, l1;
                split1(v0, h0, l0); split1(v1, h1, l1);
                *reinterpret_cast<uint32_t*>(&Ch[zC + (size_t)m0 * ldc + n]) = pack2(h0, h1);
                if (WLO) *reinterpret_cast<uint32_t*>(&Cl[zC + (size_t)m0 * ldc + n]) = pack2(l0, l1);
                split1(v2, h0, l0); split1(v3, h1, l1);
                *reinterpret_cast<uint32_t*>(&Ch[zC + (size_t)(m0 + 8) * ldc + n]) = pack2(h0, h1);
                if (WLO) *reinterpret_cast<uint32_t*>(&Cl[zC + (size_t)(m0 + 8) * ldc + n]) = pack2(l0, l1);
            }
        }
    }
}

// ===================== int8 2-digit GEMM (U = P x V^T) ======================
// C[i,j] = sA[i]*sB[j]*(16384*P11 + 128*(P10+P01)); digit planes, K contig.
// 256 thr, 8 warps (warp tile 64x32), BK=64 int8.
__global__ __launch_bounds__(256, 1) void gemm_s8d(
    const int8_t* __restrict__ Ad1, const int8_t* __restrict__ Ad0,
    const int8_t* __restrict__ Bd1, const int8_t* __restrict__ Bd0,
    const float* __restrict__ sAv, const float* __restrict__ sBv,
    long ssA, long ssB,
    float* __restrict__ Cf,
    int K, int ldc, long sA, long sB, long sC) {
    extern __shared__ __align__(16) char smem[];
    const uint32_t su = smem_u32(smem);

    constexpr int STGB = 40960;
    constexpr int BOFF = 20480;

    const int t = threadIdx.x;
    const int lane = t & 31;
    const int wid = t >> 5;
    const int warp_m = wid >> 2;   // 0..1
    const int warp_n = wid & 3;    // 0..3
    const int bi = blockIdx.y * 128;
    const int bj = blockIdx.x * 128;
    const size_t zA = (size_t)sA * blockIdx.z;
    const size_t zB = (size_t)sB * blockIdx.z;
    const size_t zC = (size_t)sC * blockIdx.z;
    const size_t zsA = (size_t)ssA * blockIdx.z;
    const size_t zsB = (size_t)ssB * blockIdx.z;

    const int row = t >> 2;        // 0..63
    const int kc = t & 3;

    auto load_stage = [&](int stage, int k0) {
        const uint32_t sb = su + stage * STGB;
#pragma unroll
        for (int i = 0; i < 2; ++i) {
            int r = row + 64 * i;
            uint32_t so = r * 80 + kc * 16;
            cp16(sb + so,         (const char*)(Ad1 + zA + (size_t)(bi + r) * K + k0) + kc * 16);
            cp16(sb + 10240 + so, (const char*)(Ad0 + zA + (size_t)(bi + r) * K + k0) + kc * 16);
            cp16(sb + BOFF + so,  (const char*)(Bd1 + zB + (size_t)(bj + r) * K + k0) + kc * 16);
            cp16(sb + 30720 + so, (const char*)(Bd0 + zB + (size_t)(bj + r) * K + k0) + kc * 16);
        }
        cp_commit();
    };

    int acc1[4][4][4] = {};
    int acc2[4][4][4] = {};
    const int T = K / 64;

    load_stage(0, 0);

    const uint32_t aoff = (uint32_t)((warp_m * 64 + (lane & 15)) * 80 + (lane >> 4) * 16);
    const uint32_t boff = (uint32_t)(BOFF + (warp_n * 32 + (lane & 15)) * 80 + (lane >> 4) * 16);

    for (int tt = 0; tt < T; ++tt) {
        cp_wait0();
        __syncthreads();
        if (tt + 1 < T) load_stage((tt + 1) & 1, (tt + 1) * 64);

        const uint32_t sb = su + (tt & 1) * STGB;
        const uint32_t aHi = sb + aoff, aLo = aHi + 10240;
        const uint32_t bHi = sb + boff, bLo = bHi + 10240;

#pragma unroll
        for (int ks = 0; ks < 2; ++ks) {
            const uint32_t kof = (uint32_t)(ks * 32);
            uint32_t b1[2][4], b0[2][4];
#pragma unroll
            for (int np = 0; np < 2; ++np) {
                ldsm4(b1[np], bHi + (uint32_t)(np * 16 * 80) + kof);
                ldsm4(b0[np], bLo + (uint32_t)(np * 16 * 80) + kof);
            }
#pragma unroll
            for (int mt = 0; mt < 4; ++mt) {
                uint32_t a1[4], a0[4];
                ldsm4(a1, aHi + (uint32_t)(mt * 16 * 80) + kof);
                ldsm4(a0, aLo + (uint32_t)(mt * 16 * 80) + kof);
#pragma unroll
                for (int nt = 0; nt < 4; ++nt) {
                    const int np = nt >> 1, j = nt & 1;
                    uint32_t e1a = b1[np][j], e1b = b1[np][2 + j];
                    mma_s8(acc1[mt][nt], a1, e1a, e1b);
                    mma_s8(acc2[mt][nt], a1, b0[np][j], b0[np][2 + j]);
                    mma_s8(acc2[mt][nt], a0, e1a, e1b);
                }
            }
        }
    }

#pragma unroll
    for (int mt = 0; mt < 4; ++mt) {
        const int m0 = bi + warp_m * 64 + mt * 16 + (lane >> 2);
        const float sa0 = sAv[zsA + m0];
        const float sa1 = sAv[zsA + m0 + 8];
#pragma unroll
        for (int nt = 0; nt < 4; ++nt) {
            const int n = bj + warp_n * 32 + nt * 8 + (lane & 3) * 2;
            const float sb0 = sBv[zsB + n];
            const float sb1 = sBv[zsB + n + 1];
            float v0 = sa0 * sb0 * (16384.f * (float)acc1[mt][nt][0] + 128.f * (float)acc2[mt][nt][0]);
            float v1 = sa0 * sb1 * (16384.f * (float)acc1[mt][nt][1] + 128.f * (float)acc2[mt][nt][1]);
            float v2 = sa1 * sb0 * (16384.f * (float)acc1[mt][nt][2] + 128.f * (float)acc2[mt][nt][2]);
            float v3 = sa1 * sb1 * (16384.f * (float)acc1[mt][nt][3] + 128.f * (float)acc2[mt][nt][3]);
            *reinterpret_cast<float2*>(&Cf[zC + (size_t)m0 * ldc + n]) = make_float2(v0, v1);
            *reinterpret_cast<float2*>(&Cf[zC + (size_t)(m0 + 8) * ldc + n]) = make_float2(v2, v3);
        }
    }
}

// ===================== V quant: rows of Vf -> digits + scale ================
__global__ __launch_bounds__(256) void v_quant() {
    const int r = blockIdx.x, b = blockIdx.y;
    const size_t base = ((size_t)b * Rr + r) * Nn;
    const int t = threadIdx.x;
    __shared__ float red[8];

    float x[16];
    float mx = 0.f;
#pragma unroll
    for (int u = 0; u < 16; ++u) {
        x[u] = g_Vf[base + t + u * 256];
        mx = fmaxf(mx, fabsf(x[u]));
    }
#pragma unroll
    for (int o = 16; o; o >>= 1) mx = fmaxf(mx, __shfl_xor_sync(0xffffffffu, mx, o));
    if ((t & 31) == 0) red[t >> 5] = mx;
    __syncthreads();
    mx = 0.f;
#pragma unroll
    for (int w = 0; w < 8; ++w) mx = fmaxf(mx, red[w]);
    mx = fmaxf(mx, 1e-20f);
    const float inv = 16256.f / mx;
#pragma unroll
    for (int u = 0; u < 16; ++u) {
        int v = __float2int_rn(x[u] * inv);
        int8_t d1, d0;
        digits(v, d1, d0);
        g_Vd1[base + t + u * 256] = d1;
        g_Vd0[base + t + u * 256] = d0;
    }
    if (t == 0) g_sV[(size_t)b * Rr + r] = mx * (1.f / 16256.f);
}

// ===================== softmax -> int8 digit planes =========================
__global__ __launch_bounds__(256) void softmax_kernel() {
    const size_t ro = (size_t)blockIdx.x * Nn;
    const float* row = g_S + ro;
    const int t = threadIdx.x;
    __shared__ float redm[8], reds[8];

    float v[16];
    float m = -1e30f;
#pragma unroll
    for (int u = 0; u < 16; ++u) {
        v[u] = row[t + u * 256];
        m = fmaxf(m, v[u]);
    }
#pragma unroll
    for (int o = 16; o; o >>= 1) m = fmaxf(m, __shfl_xor_sync(0xffffffffu, m, o));
    if ((t & 31) == 0) redm[t >> 5] = m;
    __syncthreads();
    m = redm[0];
#pragma unroll
    for (int w = 1; w < 8; ++w) m = fmaxf(m, redm[w]);

    float s = 0.f;
#pragma unroll
    for (int u = 0; u < 16; ++u) {
        v[u] = __expf(v[u] - m);
        s += v[u];
    }
#pragma unroll
    for (int o = 16; o; o >>= 1) s += __shfl_xor_sync(0xffffffffu, s, o);
    if ((t & 31) == 0) reds[t >> 5] = s;
    __syncthreads();
    float tot = 0.f;
#pragma unroll
    for (int w = 0; w < 8; ++w) tot += reds[w];
    float inv = 1.0f / tot;
    // p = v*inv, max v = 1 -> vq = round(v*16256), p = vq * (inv/16256)
#pragma unroll
    for (int u = 0; u < 16; ++u) {
        int vq = __float2int_rn(v[u] * 16256.f);
        int8_t d1, d0;
        digits(vq, d1, d0);
        g_Pd1[ro + t + u * 256] = d1;
        g_Pd0[ro + t + u * 256] = d0;
    }
    if (t == 0) g_sP[blockIdx.x] = inv * (1.f / 16256.f);
}

// ===================== add + split ==========================================
__global__ void add_kernel() {
    size_t i = ((size_t)blockIdx.x * blockDim.x + threadIdx.x) * 4;
    if (i >= NR) return;
    float4 f = *reinterpret_cast<const float4*>(&g_FTf[i]);
    float4 u = *reinterpret_cast<const float4*>(&g_UT[i]);
    float w0 = f.x + u.x, w1 = f.y + u.y, w2 = f.z + u.z, w3 = f.w + u.w;
    __nv_bfloat16 h0, l0, h1, l1, h2, l2, h3, l3;
    split1(w0, h0, l0); split1(w1, h1, l1); split1(w2, h2, l2); split1(w3, h3, l3);
    uint2 hp, lp;
    hp.x = pack2(h0, h1); hp.y = pack2(h2, h3);
    lp.x = pack2(l0, l1); lp.y = pack2(l2, l3);
    *reinterpret_cast<uint2*>(&g_WTh[i]) = hp;
    *reinterpret_cast<uint2*>(&g_WTl[i]) = lp;
}

// ===================== host =====================
constexpr int GSM = 2 * 40960;

extern "C" void kernel_launch(void* const* d_in, const int* in_sizes, int n_in,
                              void* d_out, int out_size) {
    const float* feature = (const float*)d_in[0];
    PrepArgs pa;
    for (int L = 0; L < 5; ++L) {
        pa.W[L] = (const float*)d_in[1 + 5 * L + 0];
        pa.g[L] = (const float*)d_in[1 + 5 * L + 1];
        pa.b[L] = (const float*)d_in[1 + 5 * L + 2];
        pa.m[L] = (const float*)d_in[1 + 5 * L + 3];
        pa.v[L] = (const float*)d_in[1 + 5 * L + 4];
    }

    __nv_bfloat16 *XTh, *XTl, *FTh, *FTl, *QTh, *QTl, *KTh, *KTl;
    __nv_bfloat16 *WTh, *WTl, *Wph, *Wpl;
    float *FTf, *Vf, *S, *UT, *Al, *Be, *sV, *sP;
    int8_t *Vd1, *Vd0, *Pd1, *Pd0;
    cudaGetSymbolAddress((void**)&XTh, g_XTh); cudaGetSymbolAddress((void**)&XTl, g_XTl);
    cudaGetSymbolAddress((void**)&FTh, g_FTh); cudaGetSymbolAddress((void**)&FTl, g_FTl);
    cudaGetSymbolAddress((void**)&QTh, g_QTh); cudaGetSymbolAddress((void**)&QTl, g_QTl);
    cudaGetSymbolAddress((void**)&KTh, g_KTh); cudaGetSymbolAddress((void**)&KTl, g_KTl);
    cudaGetSymbolAddress((void**)&WTh, g_WTh); cudaGetSymbolAddress((void**)&WTl, g_WTl);
    cudaGetSymbolAddress((void**)&Wph, g_Wph); cudaGetSymbolAddress((void**)&Wpl, g_Wpl);
    cudaGetSymbolAddress((void**)&FTf, g_FTf); cudaGetSymbolAddress((void**)&Vf, g_Vf);
    cudaGetSymbolAddress((void**)&S, g_S);     cudaGetSymbolAddress((void**)&UT, g_UT);
    cudaGetSymbolAddress((void**)&Al, g_alpha); cudaGetSymbolAddress((void**)&Be, g_beta);
    cudaGetSymbolAddress((void**)&sV, g_sV);   cudaGetSymbolAddress((void**)&sP, g_sP);
    cudaGetSymbolAddress((void**)&Vd1, g_Vd1); cudaGetSymbolAddress((void**)&Vd0, g_Vd0);
    cudaGetSymbolAddress((void**)&Pd1, g_Pd1); cudaGetSymbolAddress((void**)&Pd0, g_Pd0);

    cudaFuncSetAttribute(gemm_bf16s<2, true, true, true>,   cudaFuncAttributeMaxDynamicSharedMemorySize, GSM);
    cudaFuncSetAttribute(gemm_bf16s<2, false, true, true>,  cudaFuncAttributeMaxDynamicSharedMemorySize, GSM);
    cudaFuncSetAttribute(gemm_bf16s<1, true, false, false>, cudaFuncAttributeMaxDynamicSharedMemorySize, GSM);
    cudaFuncSetAttribute(gemm_bf16s<0, true, false, false>, cudaFuncAttributeMaxDynamicSharedMemorySize, GSM);
    cudaFuncSetAttribute(gemm_s8d, cudaFuncAttributeMaxDynamicSharedMemorySize, GSM);

    const long sNR = (long)Nn * Rr;
    const long sNN = (long)Nn * Nn;

    // 1) prep
    prep_kernel<<<(int)((WTOT + 4096 + 255) / 256), 256>>>(pa);

    // 2) XT = transpose+split(feature)
    xt_kernel<<<dim3(Cc / 32, Nn / 32, Bb), 256>>>(feature);

    // 3) FT = cbr-col(XT x Wr)   M=4096, N=512, K=2048
    gemm_bf16s<2, true, true, true><<<dim3(4, 32, Bb), 128, GSM>>>(
        XTh, XTl, Wph + WOF[0], Wpl + WOF[0], FTf, FTh, FTl,
        Cc, Rr, (long)Nn * Cc, 0, sNR, Al + 0 * 2048, Be + 0 * 2048);

    // 4) QT = cbr-col(FT x Wq)
    gemm_bf16s<2, false, true, true><<<dim3(4, 32, Bb), 128, GSM>>>(
        FTh, FTl, Wph + WOF[1], Wpl + WOF[1], nullptr, QTh, QTl,
        Rr, Rr, sNR, 0, sNR, Al + 1 * 2048, Be + 1 * 2048);

    // 5) KT = cbr-col(FT x Wk)
    gemm_bf16s<2, false, true, true><<<dim3(4, 32, Bb), 128, GSM>>>(
        FTh, FTl, Wph + WOF[2], Wpl + WOF[2], nullptr, KTh, KTl,
        Rr, Rr, sNR, 0, sNR, Al + 2 * 2048, Be + 2 * 2048);

    // 6) S = QT x KT^T   M=N=4096, K=512   <-- ncu capture slot (skip 5)
    gemm_bf16s<0, true, false, false><<<dim3(32, 32, Bb), 128, GSM>>>(
        QTh, QTl, KTh, KTl, S, nullptr, nullptr,
        Rr, Nn, sNR, sNR, sNN, nullptr, nullptr);

    // 7) V = cbr-row(Wv x F)   M=512, N=4096, K=512 -> fp32
    gemm_bf16s<1, true, false, false><<<dim3(32, 4, Bb), 128, GSM>>>(
        Wph + WOF[3], Wpl + WOF[3], FTh, FTl, Vf, nullptr, nullptr,
        Rr, Nn, 0, sNR, (long)Rr * Nn, Al + 3 * 2048, Be + 3 * 2048);

    // 8) quantize V rows
    v_quant<<<dim3(Rr, Bb), 256>>>();

    // 9) P = softmax rows -> digit planes
    softmax_kernel<<<Bb * Nn, 256>>>();

    // 10) UT = P x V^T   int8 digit GEMM, M=4096, N=512, K=4096
    gemm_s8d<<<dim3(4, 32, Bb), 256, GSM>>>(
        Pd1, Pd0, Vd1, Vd0, sP, sV, Nn, Rr,
        UT, Nn, Rr, sNN, (long)Rr * Nn, sNR);

    // 11) WT = split(FTf + UT)
    add_kernel<<<(int)((NR / 4 + 255) / 256), 256>>>();

    // 12) out = cbr-row(Wu x (F+U))   M=2048, N=4096, K=512
    gemm_bf16s<1, true, false, false><<<dim3(32, 16, Bb), 128, GSM>>>(
        Wph + WOF[4], Wpl + WOF[4], WTh, WTl, (float*)d_out, nullptr, nullptr,
        Rr, Nn, 0, sNR, (long)Cc * Nn, Al + 4 * 2048, Be + 4 * 2048);
}

// round 15
// speedup vs baseline: 1.1327x; 1.1327x over previous
#include <cuda_runtime.h>
#include <cuda_bf16.h>
#include <cstdint>
#include <cstddef>

#define EPS_BN 1e-5f

constexpr int Bb = 4;
constexpr int Cc = 2048;
constexpr int Rr = 512;
constexpr int Nn = 4096;   // H*W

constexpr size_t NC = (size_t)Bb * Nn * Cc;
constexpr size_t NR = (size_t)Bb * Nn * Rr;
constexpr size_t NNe = (size_t)Bb * Nn * Nn;

constexpr size_t WOF[5] = {0, 1048576, 1310720, 1572864, 1835008};
constexpr size_t WTOT = 2883584;

// ---- scratch (allocation-free) ----
__device__ __nv_bfloat16 g_XTh[NC], g_XTl[NC];
__device__ __nv_bfloat16 g_FTh[NR], g_FTl[NR];
__device__ float         g_FTf[NR];
__device__ __nv_bfloat16 g_QTh[NR], g_QTl[NR];
__device__ __nv_bfloat16 g_KTh[NR], g_KTl[NR];
__device__ __nv_bfloat16 g_Vh[NR], g_Vl[NR];
__device__ float         g_S[NNe];
__device__ __nv_bfloat16 g_Ph[NNe], g_Pl[NNe];
__device__ float         g_UT[NR];
__device__ __nv_bfloat16 g_WTh[NR], g_WTl[NR];
__device__ __nv_bfloat16 g_Wph[WTOT], g_Wpl[WTOT];
__device__ float g_alpha[5 * 2048], g_beta[5 * 2048];

// ===================== helpers =====================
__device__ __forceinline__ uint32_t smem_u32(const void* p) {
    uint32_t a;
    asm("{ .reg .u64 t; cvta.to.shared.u64 t, %1; cvt.u32.u64 %0, t; }" : "=r"(a) : "l"(p));
    return a;
}
__device__ __forceinline__ void ldsm4(uint32_t* r, uint32_t addr) {
    asm volatile("ldmatrix.sync.aligned.m8n8.x4.shared.b16 {%0,%1,%2,%3}, [%4];"
                 : "=r"(r[0]), "=r"(r[1]), "=r"(r[2]), "=r"(r[3]) : "r"(addr));
}
__device__ __forceinline__ void mma_bf16(float* c, const uint32_t* a, uint32_t b0, uint32_t b1) {
    asm volatile(
        "mma.sync.aligned.m16n8k16.row.col.f32.bf16.bf16.f32 "
        "{%0,%1,%2,%3}, {%4,%5,%6,%7}, {%8,%9}, {%0,%1,%2,%3};"
        : "+f"(c[0]), "+f"(c[1]), "+f"(c[2]), "+f"(c[3])
        : "r"(a[0]), "r"(a[1]), "r"(a[2]), "r"(a[3]), "r"(b0), "r"(b1));
}
__device__ __forceinline__ void cp16(uint32_t s, const void* g) {
    asm volatile("cp.async.cg.shared.global [%0], [%1], 16;" :: "r"(s), "l"(g));
}
__device__ __forceinline__ void cp_commit() {
    asm volatile("cp.async.commit_group;" ::: "memory");
}
__device__ __forceinline__ void cp_wait0() {
    asm volatile("cp.async.wait_group 0;" ::: "memory");
}
__device__ __forceinline__ void split1(float x, __nv_bfloat16& h, __nv_bfloat16& l) {
    h = __float2bfloat16_rn(x);
    l = __float2bfloat16_rn(x - __bfloat162float(h));
}
__device__ __forceinline__ uint32_t pack2(__nv_bfloat16 a, __nv_bfloat16 b) {
    __nv_bfloat162 p; p.x = a; p.y = b;
    return *reinterpret_cast<uint32_t*>(&p);
}

// ===================== prep =====================
struct PrepArgs {
    const float* W[5];
    const float* g[5];
    const float* b[5];
    const float* m[5];
    const float* v[5];
};

__global__ void prep_kernel(PrepArgs a) {
    const size_t wof[5] = {0, 1048576, 1310720, 1572864, 1835008};
    const int wsz[5] = {1048576, 262144, 262144, 262144, 1048576};
    int id = blockIdx.x * blockDim.x + threadIdx.x;
    if (id < 4096) {
        int L, i;
        if (id < 2048) { L = id >> 9; i = id & 511; }
        else { L = 4; i = id - 2048; }
        float al = a.g[L][i] * rsqrtf(a.v[L][i] + EPS_BN);
        g_alpha[L * 2048 + i] = al;
        g_beta[L * 2048 + i] = a.b[L][i] - a.m[L][i] * al;
        return;
    }
    size_t w = (size_t)id - 4096;
    if (w >= WTOT) return;
    int L = 0;
    size_t off = w;
    while (L < 4 && off >= (size_t)wsz[L]) { off -= wsz[L]; ++L; }
    float x = a.W[L][off];
    split1(x, g_Wph[wof[L] + off], g_Wpl[wof[L] + off]);
}

// ===================== feature transpose + split ============================
__global__ __launch_bounds__(256) void xt_kernel(const float* __restrict__ X) {
    __shared__ float s[32][33];
    const int c0 = blockIdx.x * 32;
    const int n0 = blockIdx.y * 32;
    const size_t zo = (size_t)blockIdx.z * Cc * Nn;
    const int tx = threadIdx.x & 31;
    const int ty = threadIdx.x >> 5;
#pragma unroll
    for (int i = 0; i < 4; ++i)
        s[ty + 8 * i][tx] = X[zo + (size_t)(c0 + ty + 8 * i) * Nn + n0 + tx];
    __syncthreads();
    const size_t zo2 = (size_t)blockIdx.z * Nn * Cc;
#pragma unroll
    for (int i = 0; i < 4; ++i) {
        float val = s[tx][ty + 8 * i];
        size_t o = zo2 + (size_t)(n0 + ty + 8 * i) * Cc + c0 + tx;
        split1(val, g_XTh[o], g_XTl[o]);
    }
}

// ===================== canonical split-bf16 GEMM (R8 form) ==================
template <int SCALE, bool OF32, bool OPL, bool WLO>
__global__ __launch_bounds__(128, 2) void gemm_bf16s(
    const __nv_bfloat16* __restrict__ Ah, const __nv_bfloat16* __restrict__ Al,
    const __nv_bfloat16* __restrict__ Bh, const __nv_bfloat16* __restrict__ Bl,
    float* __restrict__ Cf, __nv_bfloat16* __restrict__ Ch, __nv_bfloat16* __restrict__ Cl,
    int K, int ldc, long sA, long sB, long sC,
    const float* __restrict__ alpha, const float* __restrict__ beta) {
    extern __shared__ __align__(16) char smem[];
    const uint32_t su = smem_u32(smem);

    constexpr int STGB = 40960;
    constexpr int BOFF = 20480;

    const int t = threadIdx.x;
    const int lane = t & 31;
    const int wid = t >> 5;
    const int warp_m = wid >> 1;
    const int warp_n = wid & 1;
    const int bi = blockIdx.y * 128;
    const int bj = blockIdx.x * 128;
    const size_t zA = (size_t)sA * blockIdx.z;
    const size_t zB = (size_t)sB * blockIdx.z;
    const size_t zC = (size_t)sC * blockIdx.z;

    const int row = t >> 2;
    const int kc = t & 3;

    auto load_stage = [&](int stage, int k0) {
        const uint32_t sb = su + stage * STGB;
#pragma unroll
        for (int i = 0; i < 4; ++i) {
            int r = row + 32 * i;
            uint32_t so = r * 80 + kc * 16;
            cp16(sb + so,         (const char*)(Ah + zA + (size_t)(bi + r) * K + k0) + kc * 16);
            cp16(sb + 10240 + so, (const char*)(Al + zA + (size_t)(bi + r) * K + k0) + kc * 16);
            cp16(sb + BOFF + so,  (const char*)(Bh + zB + (size_t)(bj + r) * K + k0) + kc * 16);
            cp16(sb + 30720 + so, (const char*)(Bl + zB + (size_t)(bj + r) * K + k0) + kc * 16);
        }
        cp_commit();
    };

    float acc[4][8][4] = {};
    const int T = K / 32;

    load_stage(0, 0);

    const uint32_t aoff = (uint32_t)((warp_m * 64 + (lane & 15)) * 80 + (lane >> 4) * 16);
    const uint32_t boff = (uint32_t)(BOFF + (warp_n * 64 + (lane & 15)) * 80 + (lane >> 4) * 16);

    for (int tt = 0; tt < T; ++tt) {
        cp_wait0();
        __syncthreads();
        if (tt + 1 < T) load_stage((tt + 1) & 1, (tt + 1) * 32);

        const uint32_t sb = su + (tt & 1) * STGB;
        const uint32_t aHi = sb + aoff, aLo = aHi + 10240;
        const uint32_t bHi = sb + boff, bLo = bHi + 10240;

#pragma unroll
        for (int ks = 0; ks < 2; ++ks) {
            const uint32_t kof = (uint32_t)(ks * 32);
            uint32_t bh[4][4], bl[4][4];
#pragma unroll
            for (int np = 0; np < 4; ++np) {
                ldsm4(bh[np], bHi + (uint32_t)(np * 16 * 80) + kof);
                ldsm4(bl[np], bLo + (uint32_t)(np * 16 * 80) + kof);
            }
#pragma unroll
            for (int mt = 0; mt < 4; ++mt) {
                uint32_t ah[4], al_[4];
                ldsm4(ah, aHi + (uint32_t)(mt * 16 * 80) + kof);
                ldsm4(al_, aLo + (uint32_t)(mt * 16 * 80) + kof);
#pragma unroll
                for (int nt = 0; nt < 8; ++nt) {
                    const uint32_t* h = bh[nt >> 1];
                    const uint32_t* l = bl[nt >> 1];
                    mma_bf16(acc[mt][nt], ah, h[nt & 1], h[2 + (nt & 1)]);
                    mma_bf16(acc[mt][nt], al_, h[nt & 1], h[2 + (nt & 1)]);
                    mma_bf16(acc[mt][nt], ah, l[nt & 1], l[2 + (nt & 1)]);
                }
            }
        }
    }

#pragma unroll
    for (int mt = 0; mt < 4; ++mt) {
        const int m0 = bi + warp_m * 64 + mt * 16 + (lane >> 2);
        float ra0 = 1.f, rb0 = 0.f, ra1 = 1.f, rb1 = 0.f;
        if (SCALE == 1) {
            ra0 = alpha[m0]; rb0 = beta[m0];
            ra1 = alpha[m0 + 8]; rb1 = beta[m0 + 8];
        }
#pragma unroll
        for (int nt = 0; nt < 8; ++nt) {
            const int n = bj + warp_n * 64 + nt * 8 + (lane & 3) * 2;
            float v0 = acc[mt][nt][0], v1 = acc[mt][nt][1];
            float v2 = acc[mt][nt][2], v3 = acc[mt][nt][3];
            if (SCALE == 1) {
                v0 = fmaxf(fmaf(ra0, v0, rb0), 0.f); v1 = fmaxf(fmaf(ra0, v1, rb0), 0.f);
                v2 = fmaxf(fmaf(ra1, v2, rb1), 0.f); v3 = fmaxf(fmaf(ra1, v3, rb1), 0.f);
            } else if (SCALE == 2) {
                float ca0 = alpha[n], cb0 = beta[n], ca1 = alpha[n + 1], cb1 = beta[n + 1];
                v0 = fmaxf(fmaf(ca0, v0, cb0), 0.f); v1 = fmaxf(fmaf(ca1, v1, cb1), 0.f);
                v2 = fmaxf(fmaf(ca0, v2, cb0), 0.f); v3 = fmaxf(fmaf(ca1, v3, cb1), 0.f);
            }
            if (OF32) {
                *reinterpret_cast<float2*>(&Cf[zC + (size_t)m0 * ldc + n]) = make_float2(v0, v1);
                *reinterpret_cast<float2*>(&Cf[zC + (size_t)(m0 + 8) * ldc + n]) = make_float2(v2, v3);
            }
            if (OPL) {
                __nv_bfloat16 h0, l0, h1, l1;
                split1(v0, h0, l0); split1(v1, h1, l1);
                *reinterpret_cast<uint32_t*>(&Ch[zC + (size_t)m0 * ldc + n]) = pack2(h0, h1);
                if (WLO) *reinterpret_cast<uint32_t*>(&Cl[zC + (size_t)m0 * ldc + n]) = pack2(l0, l1);
                split1(v2, h0, l0); split1(v3, h1, l1);
                *reinterpret_cast<uint32_t*>(&Ch[zC + (size_t)(m0 + 8) * ldc + n]) = pack2(h0, h1);
                if (WLO) *reinterpret_cast<uint32_t*>(&Cl[zC + (size_t)(m0 + 8) * ldc + n]) = pack2(l0, l1);
            }
        }
    }
}

// ===================== hybrid MMA+FFMA GEMM (fp32 out only) =================
// C[i,j] = sum_k A[i,k]*B[j,k]; planes, K contig. Columns [0, NM*128) via MMA
// tiles (128x128), columns [NM*128, NM*128+NF*64) via FFMA tiles (64x64).
// Tile ids interleave both types so the CTA scheduler mixes pipes per SM.
template <int NM, int NF>
__global__ __launch_bounds__(128, 2) void gemm_hyb(
    const __nv_bfloat16* __restrict__ Ah, const __nv_bfloat16* __restrict__ Al,
    const __nv_bfloat16* __restrict__ Bh, const __nv_bfloat16* __restrict__ Bl,
    float* __restrict__ Cf,
    int M, int K, int ldc, long sA, long sB, long sC) {
    extern __shared__ __align__(16) char smem[];
    const uint32_t su = smem_u32(smem);
    const int t = threadIdx.x;
    const size_t zA = (size_t)sA * blockIdx.z;
    const size_t zB = (size_t)sB * blockIdx.z;
    const size_t zC = (size_t)sC * blockIdx.z;

    const int TM = NM * (M >> 7);
    const int TF = NF * (M >> 6);
    const int mn = TM < TF ? TM : TF;
    const int L = 2 * mn;
    const int id = blockIdx.x;
    bool is_mma;
    int idx;
    if (id < L) { is_mma = !(id & 1); idx = id >> 1; }
    else { is_mma = (TM > TF); idx = mn + (id - L); }

    if (is_mma) {
        // ---------------- MMA path (R8 body, SCALE=0, fp32 out) ----------------
        constexpr int STGB = 40960;
        constexpr int BOFF = 20480;
        const int lane = t & 31;
        const int wid = t >> 5;
        const int warp_m = wid >> 1;
        const int warp_n = wid & 1;
        const int bi = (idx / NM) * 128;
        const int bj = (idx % NM) * 128;
        const int row = t >> 2;
        const int kc = t & 3;

        auto load_stage = [&](int stage, int k0) {
            const uint32_t sb = su + stage * STGB;
#pragma unroll
            for (int i = 0; i < 4; ++i) {
                int r = row + 32 * i;
                uint32_t so = r * 80 + kc * 16;
                cp16(sb + so,         (const char*)(Ah + zA + (size_t)(bi + r) * K + k0) + kc * 16);
                cp16(sb + 10240 + so, (const char*)(Al + zA + (size_t)(bi + r) * K + k0) + kc * 16);
                cp16(sb + BOFF + so,  (const char*)(Bh + zB + (size_t)(bj + r) * K + k0) + kc * 16);
                cp16(sb + 30720 + so, (const char*)(Bl + zB + (size_t)(bj + r) * K + k0) + kc * 16);
            }
            cp_commit();
        };

        float acc[4][8][4] = {};
        const int T = K / 32;
        load_stage(0, 0);

        const uint32_t aoff = (uint32_t)((warp_m * 64 + (lane & 15)) * 80 + (lane >> 4) * 16);
        const uint32_t boff = (uint32_t)(BOFF + (warp_n * 64 + (lane & 15)) * 80 + (lane >> 4) * 16);

        for (int tt = 0; tt < T; ++tt) {
            cp_wait0();
            __syncthreads();
            if (tt + 1 < T) load_stage((tt + 1) & 1, (tt + 1) * 32);

            const uint32_t sb = su + (tt & 1) * STGB;
            const uint32_t aHi = sb + aoff, aLo = aHi + 10240;
            const uint32_t bHi = sb + boff, bLo = bHi + 10240;

#pragma unroll
            for (int ks = 0; ks < 2; ++ks) {
                const uint32_t kof = (uint32_t)(ks * 32);
                uint32_t bh[4][4], bl[4][4];
#pragma unroll
                for (int np = 0; np < 4; ++np) {
                    ldsm4(bh[np], bHi + (uint32_t)(np * 16 * 80) + kof);
                    ldsm4(bl[np], bLo + (uint32_t)(np * 16 * 80) + kof);
                }
#pragma unroll
                for (int mt = 0; mt < 4; ++mt) {
                    uint32_t ah[4], al_[4];
                    ldsm4(ah, aHi + (uint32_t)(mt * 16 * 80) + kof);
                    ldsm4(al_, aLo + (uint32_t)(mt * 16 * 80) + kof);
#pragma unroll
                    for (int nt = 0; nt < 8; ++nt) {
                        const uint32_t* h = bh[nt >> 1];
                        const uint32_t* l = bl[nt >> 1];
                        mma_bf16(acc[mt][nt], ah, h[nt & 1], h[2 + (nt & 1)]);
                        mma_bf16(acc[mt][nt], al_, h[nt & 1], h[2 + (nt & 1)]);
                        mma_bf16(acc[mt][nt], ah, l[nt & 1], l[2 + (nt & 1)]);
                    }
                }
            }
        }

#pragma unroll
        for (int mt = 0; mt < 4; ++mt) {
            const int m0 = bi + warp_m * 64 + mt * 16 + (lane >> 2);
#pragma unroll
            for (int nt = 0; nt < 8; ++nt) {
                const int n = bj + warp_n * 64 + nt * 8 + (lane & 3) * 2;
                *reinterpret_cast<float2*>(&Cf[zC + (size_t)m0 * ldc + n]) =
                    make_float2(acc[mt][nt][0], acc[mt][nt][1]);
                *reinterpret_cast<float2*>(&Cf[zC + (size_t)(m0 + 8) * ldc + n]) =
                    make_float2(acc[mt][nt][2], acc[mt][nt][3]);
            }
        }
    } else {
        // ---------------- FFMA path (64x64 tile, fp32 via hi+lo) ----------------
        const int bi = (idx / NF) * 64;
        const int bj = NM * 128 + (idx % NF) * 64;
        float* sAf = reinterpret_cast<float*>(smem);           // [16][72]
        float* sBf = sAf + 16 * 72;                             // [16][72]

        const int r = t >> 1;          // 0..63
        const int kh = (t & 1) * 8;    // 0 or 8
        const int tx = t & 15;         // cols tx*4
        const int ty = t >> 4;         // rows ty*8

        float ar[8], br[8];
        float acc[8][4] = {};

        auto ldgf = [&](int k0) {
            uint4 h4 = *reinterpret_cast<const uint4*>(Ah + zA + (size_t)(bi + r) * K + k0 + kh);
            uint4 l4 = *reinterpret_cast<const uint4*>(Al + zA + (size_t)(bi + r) * K + k0 + kh);
            const __nv_bfloat162* hp = reinterpret_cast<const __nv_bfloat162*>(&h4);
            const __nv_bfloat162* lp = reinterpret_cast<const __nv_bfloat162*>(&l4);
#pragma unroll
            for (int j = 0; j < 4; ++j) {
                float2 hf = __bfloat1622float2(hp[j]);
                float2 lf = __bfloat1622float2(lp[j]);
                ar[2 * j] = hf.x + lf.x;
                ar[2 * j + 1] = hf.y + lf.y;
            }
            uint4 bh4 = *reinterpret_cast<const uint4*>(Bh + zB + (size_t)(bj + r) * K + k0 + kh);
            uint4 bl4 = *reinterpret_cast<const uint4*>(Bl + zB + (size_t)(bj + r) * K + k0 + kh);
            hp = reinterpret_cast<const __nv_bfloat162*>(&bh4);
            lp = reinterpret_cast<const __nv_bfloat162*>(&bl4);
#pragma unroll
            for (int j = 0; j < 4; ++j) {
                float2 hf = __bfloat1622float2(hp[j]);
                float2 lf = __bfloat1622float2(lp[j]);
                br[2 * j] = hf.x + lf.x;
                br[2 * j + 1] = hf.y + lf.y;
            }
        };

        ldgf(0);
        const int TT = K / 16;
        for (int tt = 0; tt < TT; ++tt) {
#pragma unroll
            for (int j = 0; j < 8; ++j) {
                sAf[(kh + j) * 72 + r] = ar[j];
                sBf[(kh + j) * 72 + r] = br[j];
            }
            __syncthreads();
            if (tt + 1 < TT) ldgf((tt + 1) * 16);
#pragma unroll
            for (int k = 0; k < 16; ++k) {
                float4 a0 = *reinterpret_cast<const float4*>(&sAf[k * 72 + ty * 8]);
                float4 a1 = *reinterpret_cast<const float4*>(&sAf[k * 72 + ty * 8 + 4]);
                float4 bv = *reinterpret_cast<const float4*>(&sBf[k * 72 + tx * 4]);
                float av[8] = {a0.x, a0.y, a0.z, a0.w, a1.x, a1.y, a1.z, a1.w};
                float bb[4] = {bv.x, bv.y, bv.z, bv.w};
#pragma unroll
                for (int i = 0; i < 8; ++i)
#pragma unroll
                    for (int j = 0; j < 4; ++j) acc[i][j] += av[i] * bb[j];
            }
            __syncthreads();
        }
#pragma unroll
        for (int i = 0; i < 8; ++i) {
            float4 o = make_float4(acc[i][0], acc[i][1], acc[i][2], acc[i][3]);
            *reinterpret_cast<float4*>(
                &Cf[zC + (size_t)(bi + ty * 8 + i) * ldc + bj + tx * 4]) = o;
        }
    }
}

// ===================== softmax -> split planes ==============================
__global__ __launch_bounds__(256) void softmax_kernel() {
    const size_t ro = (size_t)blockIdx.x * Nn;
    const float* row = g_S + ro;
    const int t = threadIdx.x;
    __shared__ float redm[8], reds[8];

    float v[16];
    float m = -1e30f;
#pragma unroll
    for (int u = 0; u < 16; ++u) {
        v[u] = row[t + u * 256];
        m = fmaxf(m, v[u]);
    }
#pragma unroll
    for (int o = 16; o; o >>= 1) m = fmaxf(m, __shfl_xor_sync(0xffffffffu, m, o));
    if ((t & 31) == 0) redm[t >> 5] = m;
    __syncthreads();
    m = redm[0];
#pragma unroll
    for (int w = 1; w < 8; ++w) m = fmaxf(m, redm[w]);

    float s = 0.f;
#pragma unroll
    for (int u = 0; u < 16; ++u) {
        v[u] = __expf(v[u] - m);
        s += v[u];
    }
#pragma unroll
    for (int o = 16; o; o >>= 1) s += __shfl_xor_sync(0xffffffffu, s, o);
    if ((t & 31) == 0) reds[t >> 5] = s;
    __syncthreads();
    float tot = 0.f;
#pragma unroll
    for (int w = 0; w < 8; ++w) tot += reds[w];
    float inv = 1.0f / tot;
#pragma unroll
    for (int u = 0; u < 16; ++u) {
        float p = v[u] * inv;
        split1(p, g_Ph[ro + t + u * 256], g_Pl[ro + t + u * 256]);
    }
}

// ===================== add + split ==========================================
__global__ void add_kernel() {
    size_t i = ((size_t)blockIdx.x * blockDim.x + threadIdx.x) * 4;
    if (i >= NR) return;
    float4 f = *reinterpret_cast<const float4*>(&g_FTf[i]);
    float4 u = *reinterpret_cast<const float4*>(&g_UT[i]);
    float w0 = f.x + u.x, w1 = f.y + u.y, w2 = f.z + u.z, w3 = f.w + u.w;
    __nv_bfloat16 h0, l0, h1, l1, h2, l2, h3, l3;
    split1(w0, h0, l0); split1(w1, h1, l1); split1(w2, h2, l2); split1(w3, h3, l3);
    uint2 hp, lp;
    hp.x = pack2(h0, h1); hp.y = pack2(h2, h3);
    lp.x = pack2(l0, l1); lp.y = pack2(l2, l3);
    *reinterpret_cast<uint2*>(&g_WTh[i]) = hp;
    *reinterpret_cast<uint2*>(&g_WTl[i]) = lp;
}

// ===================== host =====================
constexpr int GSM = 2 * 40960;

extern "C" void kernel_launch(void* const* d_in, const int* in_sizes, int n_in,
                              void* d_out, int out_size) {
    const float* feature = (const float*)d_in[0];
    PrepArgs pa;
    for (int L = 0; L < 5; ++L) {
        pa.W[L] = (const float*)d_in[1 + 5 * L + 0];
        pa.g[L] = (const float*)d_in[1 + 5 * L + 1];
        pa.b[L] = (const float*)d_in[1 + 5 * L + 2];
        pa.m[L] = (const float*)d_in[1 + 5 * L + 3];
        pa.v[L] = (const float*)d_in[1 + 5 * L + 4];
    }

    __nv_bfloat16 *XTh, *XTl, *FTh, *FTl, *QTh, *QTl, *KTh, *KTl, *Vh, *Vl;
    __nv_bfloat16 *Ph, *Pl, *WTh, *WTl, *Wph, *Wpl;
    float *FTf, *S, *UT, *Al, *Be;
    cudaGetSymbolAddress((void**)&XTh, g_XTh); cudaGetSymbolAddress((void**)&XTl, g_XTl);
    cudaGetSymbolAddress((void**)&FTh, g_FTh); cudaGetSymbolAddress((void**)&FTl, g_FTl);
    cudaGetSymbolAddress((void**)&QTh, g_QTh); cudaGetSymbolAddress((void**)&QTl, g_QTl);
    cudaGetSymbolAddress((void**)&KTh, g_KTh); cudaGetSymbolAddress((void**)&KTl, g_KTl);
    cudaGetSymbolAddress((void**)&Vh, g_Vh);   cudaGetSymbolAddress((void**)&Vl, g_Vl);
    cudaGetSymbolAddress((void**)&Ph, g_Ph);   cudaGetSymbolAddress((void**)&Pl, g_Pl);
    cudaGetSymbolAddress((void**)&WTh, g_WTh); cudaGetSymbolAddress((void**)&WTl, g_WTl);
    cudaGetSymbolAddress((void**)&Wph, g_Wph); cudaGetSymbolAddress((void**)&Wpl, g_Wpl);
    cudaGetSymbolAddress((void**)&FTf, g_FTf); cudaGetSymbolAddress((void**)&S, g_S);
    cudaGetSymbolAddress((void**)&UT, g_UT);
    cudaGetSymbolAddress((void**)&Al, g_alpha); cudaGetSymbolAddress((void**)&Be, g_beta);

    cudaFuncSetAttribute(gemm_bf16s<2, true, true, true>,   cudaFuncAttributeMaxDynamicSharedMemorySize, GSM);
    cudaFuncSetAttribute(gemm_bf16s<2, false, true, true>,  cudaFuncAttributeMaxDynamicSharedMemorySize, GSM);
    cudaFuncSetAttribute(gemm_bf16s<1, false, true, true>,  cudaFuncAttributeMaxDynamicSharedMemorySize, GSM);
    cudaFuncSetAttribute(gemm_bf16s<1, true, false, false>, cudaFuncAttributeMaxDynamicSharedMemorySize, GSM);
    cudaFuncSetAttribute(gemm_hyb<26, 12>, cudaFuncAttributeMaxDynamicSharedMemorySize, GSM);
    cudaFuncSetAttribute(gemm_hyb<3, 2>,   cudaFuncAttributeMaxDynamicSharedMemorySize, GSM);

    const long sNR = (long)Nn * Rr;
    const long sNN = (long)Nn * Nn;

    // 1) prep
    prep_kernel<<<(int)((WTOT + 4096 + 255) / 256), 256>>>(pa);

    // 2) XT = transpose+split(feature)
    xt_kernel<<<dim3(Cc / 32, Nn / 32, Bb), 256>>>(feature);

    // 3) FT = cbr-col(XT x Wr)   M=4096, N=512, K=2048
    gemm_bf16s<2, true, true, true><<<dim3(4, 32, Bb), 128, GSM>>>(
        XTh, XTl, Wph + WOF[0], Wpl + WOF[0], FTf, FTh, FTl,
        Cc, Rr, (long)Nn * Cc, 0, sNR, Al + 0 * 2048, Be + 0 * 2048);

    // 4) QT = cbr-col(FT x Wq)
    gemm_bf16s<2, false, true, true><<<dim3(4, 32, Bb), 128, GSM>>>(
        FTh, FTl, Wph + WOF[1], Wpl + WOF[1], nullptr, QTh, QTl,
        Rr, Rr, sNR, 0, sNR, Al + 1 * 2048, Be + 1 * 2048);

    // 5) KT = cbr-col(FT x Wk)
    gemm_bf16s<2, false, true, true><<<dim3(4, 32, Bb), 128, GSM>>>(
        FTh, FTl, Wph + WOF[2], Wpl + WOF[2], nullptr, KTh, KTl,
        Rr, Rr, sNR, 0, sNR, Al + 2 * 2048, Be + 2 * 2048);

    // 6) S = QT x KT^T  HYBRID  M=4096, K=512, cols: 3328 MMA + 768 FFMA
    {
        const int TM = 26 * (Nn / 128), TF = 12 * (Nn / 64);
        gemm_hyb<26, 12><<<dim3(TM + TF, 1, Bb), 128, GSM>>>(
            QTh, QTl, KTh, KTl, S, Nn, Rr, Nn, sNR, sNR, sNN);
    }

    // 7) V = cbr-row(Wv x F)   M=512, N=4096, K=512 -> planes
    gemm_bf16s<1, false, true, true><<<dim3(32, 4, Bb), 128, GSM>>>(
        Wph + WOF[3], Wpl + WOF[3], FTh, FTl, nullptr, Vh, Vl,
        Rr, Nn, 0, sNR, (long)Rr * Nn, Al + 3 * 2048, Be + 3 * 2048);

    // 8) P = softmax rows -> split planes
    softmax_kernel<<<Bb * Nn, 256>>>();

    // 9) UT = P x V^T  HYBRID  M=4096, K=4096, cols: 384 MMA + 128 FFMA
    {
        const int TM = 3 * (Nn / 128), TF = 2 * (Nn / 64);
        gemm_hyb<3, 2><<<dim3(TM + TF, 1, Bb), 128, GSM>>>(
            Ph, Pl, Vh, Vl, UT, Nn, Nn, Rr, sNN, (long)Rr * Nn, sNR);
    }

    // 10) WT = split(FTf + UT)
    add_kernel<<<(int)((NR / 4 + 255) / 256), 256>>>();

    // 11) out = cbr-row(Wu x (F+U))   M=2048, N=4096, K=512
    gemm_bf16s<1, true, false, false><<<dim3(32, 16, Bb), 128, GSM>>>(
        Wph + WOF[4], Wpl + WOF[4], WTh, WTl, (float*)d_out, nullptr, nullptr,
        Rr, Nn, 0, sNR, (long)Cc * Nn, Al + 4 * 2048, Be + 4 * 2048);
}

// round 16
// speedup vs baseline: 1.7004x; 1.5013x over previous
#include <cuda_runtime.h>
#include <cuda_bf16.h>
#include <cuda_fp16.h>
#include <cstdint>
#include <cstddef>

#define EPS_BN 1e-5f

constexpr int Bb = 4;
constexpr int Cc = 2048;
constexpr int Rr = 512;
constexpr int Nn = 4096;   // H*W

constexpr size_t NC = (size_t)Bb * Nn * Cc;
constexpr size_t NR = (size_t)Bb * Nn * Rr;
constexpr size_t NNe = (size_t)Bb * Nn * Nn;

constexpr size_t WOF[5] = {0, 1048576, 1310720, 1572864, 1835008};
constexpr size_t WTOT = 2883584;

// ---- scratch (allocation-free) ----
__device__ __nv_bfloat16 g_XTh[NC], g_XTl[NC];
__device__ __nv_bfloat16 g_FTh[NR], g_FTl[NR];
__device__ float         g_FTf[NR];
__device__ __nv_bfloat16 g_QTh[NR], g_QTl[NR];
__device__ __nv_bfloat16 g_KTh[NR], g_KTl[NR];
__device__ __half        g_V16[NR];                 // V fp16 [B][R][N]
__device__ float         g_S[NNe];
__device__ __half        g_P16[NNe];                // softmax fp16 [B][N][N]
__device__ float         g_UT[NR];
__device__ __nv_bfloat16 g_WTh[NR], g_WTl[NR];
__device__ __nv_bfloat16 g_Wph[WTOT], g_Wpl[WTOT];
__device__ float g_alpha[5 * 2048], g_beta[5 * 2048];

// ===================== helpers =====================
__device__ __forceinline__ uint32_t smem_u32(const void* p) {
    uint32_t a;
    asm("{ .reg .u64 t; cvta.to.shared.u64 t, %1; cvt.u32.u64 %0, t; }" : "=r"(a) : "l"(p));
    return a;
}
__device__ __forceinline__ void ldsm4(uint32_t* r, uint32_t addr) {
    asm volatile("ldmatrix.sync.aligned.m8n8.x4.shared.b16 {%0,%1,%2,%3}, [%4];"
                 : "=r"(r[0]), "=r"(r[1]), "=r"(r[2]), "=r"(r[3]) : "r"(addr));
}
__device__ __forceinline__ void mma_bf16(float* c, const uint32_t* a, uint32_t b0, uint32_t b1) {
    asm volatile(
        "mma.sync.aligned.m16n8k16.row.col.f32.bf16.bf16.f32 "
        "{%0,%1,%2,%3}, {%4,%5,%6,%7}, {%8,%9}, {%0,%1,%2,%3};"
        : "+f"(c[0]), "+f"(c[1]), "+f"(c[2]), "+f"(c[3])
        : "r"(a[0]), "r"(a[1]), "r"(a[2]), "r"(a[3]), "r"(b0), "r"(b1));
}
__device__ __forceinline__ void mma_f16(float* c, const uint32_t* a, uint32_t b0, uint32_t b1) {
    asm volatile(
        "mma.sync.aligned.m16n8k16.row.col.f32.f16.f16.f32 "
        "{%0,%1,%2,%3}, {%4,%5,%6,%7}, {%8,%9}, {%0,%1,%2,%3};"
        : "+f"(c[0]), "+f"(c[1]), "+f"(c[2]), "+f"(c[3])
        : "r"(a[0]), "r"(a[1]), "r"(a[2]), "r"(a[3]), "r"(b0), "r"(b1));
}
__device__ __forceinline__ void cp16(uint32_t s, const void* g) {
    asm volatile("cp.async.cg.shared.global [%0], [%1], 16;" :: "r"(s), "l"(g));
}
__device__ __forceinline__ void cp_commit() {
    asm volatile("cp.async.commit_group;" ::: "memory");
}
__device__ __forceinline__ void cp_wait0() {
    asm volatile("cp.async.wait_group 0;" ::: "memory");
}
__device__ __forceinline__ void split1(float x, __nv_bfloat16& h, __nv_bfloat16& l) {
    h = __float2bfloat16_rn(x);
    l = __float2bfloat16_rn(x - __bfloat162float(h));
}
__device__ __forceinline__ uint32_t pack2(__nv_bfloat16 a, __nv_bfloat16 b) {
    __nv_bfloat162 p; p.x = a; p.y = b;
    return *reinterpret_cast<uint32_t*>(&p);
}
__device__ __forceinline__ uint32_t pack2h(float a, float b) {
    __half2 p = __floats2half2_rn(a, b);
    return *reinterpret_cast<uint32_t*>(&p);
}

// ===================== prep =====================
struct PrepArgs {
    const float* W[5];
    const float* g[5];
    const float* b[5];
    const float* m[5];
    const float* v[5];
};

__global__ void prep_kernel(PrepArgs a) {
    const size_t wof[5] = {0, 1048576, 1310720, 1572864, 1835008};
    const int wsz[5] = {1048576, 262144, 262144, 262144, 1048576};
    int id = blockIdx.x * blockDim.x + threadIdx.x;
    if (id < 4096) {
        int L, i;
        if (id < 2048) { L = id >> 9; i = id & 511; }
        else { L = 4; i = id - 2048; }
        float al = a.g[L][i] * rsqrtf(a.v[L][i] + EPS_BN);
        g_alpha[L * 2048 + i] = al;
        g_beta[L * 2048 + i] = a.b[L][i] - a.m[L][i] * al;
        return;
    }
    size_t w = (size_t)id - 4096;
    if (w >= WTOT) return;
    int L = 0;
    size_t off = w;
    while (L < 4 && off >= (size_t)wsz[L]) { off -= wsz[L]; ++L; }
    float x = a.W[L][off];
    split1(x, g_Wph[wof[L] + off], g_Wpl[wof[L] + off]);
}

// ===================== feature transpose + split ============================
__global__ __launch_bounds__(256) void xt_kernel(const float* __restrict__ X) {
    __shared__ float s[32][33];
    const int c0 = blockIdx.x * 32;
    const int n0 = blockIdx.y * 32;
    const size_t zo = (size_t)blockIdx.z * Cc * Nn;
    const int tx = threadIdx.x & 31;
    const int ty = threadIdx.x >> 5;
#pragma unroll
    for (int i = 0; i < 4; ++i)
        s[ty + 8 * i][tx] = X[zo + (size_t)(c0 + ty + 8 * i) * Nn + n0 + tx];
    __syncthreads();
    const size_t zo2 = (size_t)blockIdx.z * Nn * Cc;
#pragma unroll
    for (int i = 0; i < 4; ++i) {
        float val = s[tx][ty + 8 * i];
        size_t o = zo2 + (size_t)(n0 + ty + 8 * i) * Cc + c0 + tx;
        split1(val, g_XTh[o], g_XTl[o]);
    }
}

// ===================== canonical split-bf16 GEMM (R8 form) ==================
// C[i,j] = sum_k A[i,k]*B[j,k];  A planes [M][K], B planes [N][K] (K contig).
// SCALE: 0 none, 1 row alpha[i], 2 col alpha[j]; >0 implies ReLU.
// OPL: write plane output; H16: plane output is fp16 single plane (Ch only).
template <int SCALE, bool OF32, bool OPL, bool WLO, bool H16>
__global__ __launch_bounds__(128, 2) void gemm_bf16s(
    const __nv_bfloat16* __restrict__ Ah, const __nv_bfloat16* __restrict__ Al,
    const __nv_bfloat16* __restrict__ Bh, const __nv_bfloat16* __restrict__ Bl,
    float* __restrict__ Cf, __nv_bfloat16* __restrict__ Ch, __nv_bfloat16* __restrict__ Cl,
    int K, int ldc, long sA, long sB, long sC,
    const float* __restrict__ alpha, const float* __restrict__ beta) {
    extern __shared__ __align__(16) char smem[];
    const uint32_t su = smem_u32(smem);

    constexpr int STGB = 40960;
    constexpr int BOFF = 20480;

    const int t = threadIdx.x;
    const int lane = t & 31;
    const int wid = t >> 5;
    const int warp_m = wid >> 1;
    const int warp_n = wid & 1;
    const int bi = blockIdx.y * 128;
    const int bj = blockIdx.x * 128;
    const size_t zA = (size_t)sA * blockIdx.z;
    const size_t zB = (size_t)sB * blockIdx.z;
    const size_t zC = (size_t)sC * blockIdx.z;

    const int row = t >> 2;
    const int kc = t & 3;

    auto load_stage = [&](int stage, int k0) {
        const uint32_t sb = su + stage * STGB;
#pragma unroll
        for (int i = 0; i < 4; ++i) {
            int r = row + 32 * i;
            uint32_t so = r * 80 + kc * 16;
            cp16(sb + so,         (const char*)(Ah + zA + (size_t)(bi + r) * K + k0) + kc * 16);
            cp16(sb + 10240 + so, (const char*)(Al + zA + (size_t)(bi + r) * K + k0) + kc * 16);
            cp16(sb + BOFF + so,  (const char*)(Bh + zB + (size_t)(bj + r) * K + k0) + kc * 16);
            cp16(sb + 30720 + so, (const char*)(Bl + zB + (size_t)(bj + r) * K + k0) + kc * 16);
        }
        cp_commit();
    };

    float acc[4][8][4] = {};
    const int T = K / 32;

    load_stage(0, 0);

    const uint32_t aoff = (uint32_t)((warp_m * 64 + (lane & 15)) * 80 + (lane >> 4) * 16);
    const uint32_t boff = (uint32_t)(BOFF + (warp_n * 64 + (lane & 15)) * 80 + (lane >> 4) * 16);

    for (int tt = 0; tt < T; ++tt) {
        cp_wait0();
        __syncthreads();
        if (tt + 1 < T) load_stage((tt + 1) & 1, (tt + 1) * 32);

        const uint32_t sb = su + (tt & 1) * STGB;
        const uint32_t aHi = sb + aoff, aLo = aHi + 10240;
        const uint32_t bHi = sb + boff, bLo = bHi + 10240;

#pragma unroll
        for (int ks = 0; ks < 2; ++ks) {
            const uint32_t kof = (uint32_t)(ks * 32);
            uint32_t bh[4][4], bl[4][4];
#pragma unroll
            for (int np = 0; np < 4; ++np) {
                ldsm4(bh[np], bHi + (uint32_t)(np * 16 * 80) + kof);
                ldsm4(bl[np], bLo + (uint32_t)(np * 16 * 80) + kof);
            }
#pragma unroll
            for (int mt = 0; mt < 4; ++mt) {
                uint32_t ah[4], al_[4];
                ldsm4(ah, aHi + (uint32_t)(mt * 16 * 80) + kof);
                ldsm4(al_, aLo + (uint32_t)(mt * 16 * 80) + kof);
#pragma unroll
                for (int nt = 0; nt < 8; ++nt) {
                    const uint32_t* h = bh[nt >> 1];
                    const uint32_t* l = bl[nt >> 1];
                    mma_bf16(acc[mt][nt], ah, h[nt & 1], h[2 + (nt & 1)]);
                    mma_bf16(acc[mt][nt], al_, h[nt & 1], h[2 + (nt & 1)]);
                    mma_bf16(acc[mt][nt], ah, l[nt & 1], l[2 + (nt & 1)]);
                }
            }
        }
    }

#pragma unroll
    for (int mt = 0; mt < 4; ++mt) {
        const int m0 = bi + warp_m * 64 + mt * 16 + (lane >> 2);
        float ra0 = 1.f, rb0 = 0.f, ra1 = 1.f, rb1 = 0.f;
        if (SCALE == 1) {
            ra0 = alpha[m0]; rb0 = beta[m0];
            ra1 = alpha[m0 + 8]; rb1 = beta[m0 + 8];
        }
#pragma unroll
        for (int nt = 0; nt < 8; ++nt) {
            const int n = bj + warp_n * 64 + nt * 8 + (lane & 3) * 2;
            float v0 = acc[mt][nt][0], v1 = acc[mt][nt][1];
            float v2 = acc[mt][nt][2], v3 = acc[mt][nt][3];
            if (SCALE == 1) {
                v0 = fmaxf(fmaf(ra0, v0, rb0), 0.f); v1 = fmaxf(fmaf(ra0, v1, rb0), 0.f);
                v2 = fmaxf(fmaf(ra1, v2, rb1), 0.f); v3 = fmaxf(fmaf(ra1, v3, rb1), 0.f);
            } else if (SCALE == 2) {
                float ca0 = alpha[n], cb0 = beta[n], ca1 = alpha[n + 1], cb1 = beta[n + 1];
                v0 = fmaxf(fmaf(ca0, v0, cb0), 0.f); v1 = fmaxf(fmaf(ca1, v1, cb1), 0.f);
                v2 = fmaxf(fmaf(ca0, v2, cb0), 0.f); v3 = fmaxf(fmaf(ca1, v3, cb1), 0.f);
            }
            if (OF32) {
                *reinterpret_cast<float2*>(&Cf[zC + (size_t)m0 * ldc + n]) = make_float2(v0, v1);
                *reinterpret_cast<float2*>(&Cf[zC + (size_t)(m0 + 8) * ldc + n]) = make_float2(v2, v3);
            }
            if (OPL) {
                if (H16) {
                    *reinterpret_cast<uint32_t*>(&Ch[zC + (size_t)m0 * ldc + n]) = pack2h(v0, v1);
                    *reinterpret_cast<uint32_t*>(&Ch[zC + (size_t)(m0 + 8) * ldc + n]) = pack2h(v2, v3);
                } else {
                    __nv_bfloat16 h0, l0, h1, l1;
                    split1(v0, h0, l0); split1(v1, h1, l1);
                    *reinterpret_cast<uint32_t*>(&Ch[zC + (size_t)m0 * ldc + n]) = pack2(h0, h1);
                    if (WLO) *reinterpret_cast<uint32_t*>(&Cl[zC + (size_t)m0 * ldc + n]) = pack2(l0, l1);
                    split1(v2, h0, l0); split1(v3, h1, l1);
                    *reinterpret_cast<uint32_t*>(&Ch[zC + (size_t)(m0 + 8) * ldc + n]) = pack2(h0, h1);
                    if (WLO) *reinterpret_cast<uint32_t*>(&Cl[zC + (size_t)(m0 + 8) * ldc + n]) = pack2(l0, l1);
                }
            }
        }
    }
}

// ===================== single-product fp16 GEMM (U = P x V^T) ===============
// C[i,j] = sum_k A[i,k]*B[j,k]; A [M][K] fp16, B [N][K] fp16, C fp32.
// Same geometry as bf16 engine: 128x128xBK32, 128 thr, warp tile 64x64.
__global__ __launch_bounds__(128, 2) void gemm_f16(
    const __half* __restrict__ A, const __half* __restrict__ B,
    float* __restrict__ Cf,
    int K, int ldc, long sA, long sB, long sC) {
    extern __shared__ __align__(16) char smem[];
    const uint32_t su = smem_u32(smem);

    constexpr int STGB = 20480;     // A,B @ 10240 each
    constexpr int BOFF = 10240;

    const int t = threadIdx.x;
    const int lane = t & 31;
    const int wid = t >> 5;
    const int warp_m = wid >> 1;
    const int warp_n = wid & 1;
    const int bi = blockIdx.y * 128;
    const int bj = blockIdx.x * 128;
    const size_t zA = (size_t)sA * blockIdx.z;
    const size_t zB = (size_t)sB * blockIdx.z;
    const size_t zC = (size_t)sC * blockIdx.z;

    const int row = t >> 2;
    const int kc = t & 3;

    auto load_stage = [&](int stage, int k0) {
        const uint32_t sb = su + stage * STGB;
#pragma unroll
        for (int i = 0; i < 4; ++i) {
            int r = row + 32 * i;
            uint32_t so = r * 80 + kc * 16;
            cp16(sb + so,        (const char*)(A + zA + (size_t)(bi + r) * K + k0) + kc * 16);
            cp16(sb + BOFF + so, (const char*)(B + zB + (size_t)(bj + r) * K + k0) + kc * 16);
        }
        cp_commit();
    };

    float acc[4][8][4] = {};
    const int T = K / 32;

    load_stage(0, 0);

    const uint32_t aoff = (uint32_t)((warp_m * 64 + (lane & 15)) * 80 + (lane >> 4) * 16);
    const uint32_t boff = (uint32_t)(BOFF + (warp_n * 64 + (lane & 15)) * 80 + (lane >> 4) * 16);

    for (int tt = 0; tt < T; ++tt) {
        cp_wait0();
        __syncthreads();
        if (tt + 1 < T) load_stage((tt + 1) & 1, (tt + 1) * 32);

        const uint32_t sb = su + (tt & 1) * STGB;
        const uint32_t aBase = sb + aoff;
        const uint32_t bBase = sb + boff;

#pragma unroll
        for (int ks = 0; ks < 2; ++ks) {
            const uint32_t kof = (uint32_t)(ks * 32);
            uint32_t bh[4][4];
#pragma unroll
            for (int np = 0; np < 4; ++np)
                ldsm4(bh[np], bBase + (uint32_t)(np * 16 * 80) + kof);
#pragma unroll
            for (int mt = 0; mt < 4; ++mt) {
                uint32_t ah[4];
                ldsm4(ah, aBase + (uint32_t)(mt * 16 * 80) + kof);
#pragma unroll
                for (int nt = 0; nt < 8; ++nt) {
                    const uint32_t* h = bh[nt >> 1];
                    mma_f16(acc[mt][nt], ah, h[nt & 1], h[2 + (nt & 1)]);
                }
            }
        }
    }

#pragma unroll
    for (int mt = 0; mt < 4; ++mt) {
        const int m0 = bi + warp_m * 64 + mt * 16 + (lane >> 2);
#pragma unroll
        for (int nt = 0; nt < 8; ++nt) {
            const int n = bj + warp_n * 64 + nt * 8 + (lane & 3) * 2;
            *reinterpret_cast<float2*>(&Cf[zC + (size_t)m0 * ldc + n]) =
                make_float2(acc[mt][nt][0], acc[mt][nt][1]);
            *reinterpret_cast<float2*>(&Cf[zC + (size_t)(m0 + 8) * ldc + n]) =
                make_float2(acc[mt][nt][2], acc[mt][nt][3]);
        }
    }
}

// ===================== softmax -> fp16 plane ================================
__global__ __launch_bounds__(256) void softmax_kernel() {
    const size_t ro = (size_t)blockIdx.x * Nn;
    const float* row = g_S + ro;
    const int t = threadIdx.x;
    __shared__ float redm[8], reds[8];

    float v[16];
    float m = -1e30f;
#pragma unroll
    for (int u = 0; u < 16; ++u) {
        v[u] = row[t + u * 256];
        m = fmaxf(m, v[u]);
    }
#pragma unroll
    for (int o = 16; o; o >>= 1) m = fmaxf(m, __shfl_xor_sync(0xffffffffu, m, o));
    if ((t & 31) == 0) redm[t >> 5] = m;
    __syncthreads();
    m = redm[0];
#pragma unroll
    for (int w = 1; w < 8; ++w) m = fmaxf(m, redm[w]);

    float s = 0.f;
#pragma unroll
    for (int u = 0; u < 16; ++u) {
        v[u] = __expf(v[u] - m);
        s += v[u];
    }
#pragma unroll
    for (int o = 16; o; o >>= 1) s += __shfl_xor_sync(0xffffffffu, s, o);
    if ((t & 31) == 0) reds[t >> 5] = s;
    __syncthreads();
    float tot = 0.f;
#pragma unroll
    for (int w = 0; w < 8; ++w) tot += reds[w];
    float inv = 1.0f / tot;
#pragma unroll
    for (int u = 0; u < 16; ++u)
        g_P16[ro + t + u * 256] = __float2half_rn(v[u] * inv);
}

// ===================== add + split ==========================================
__global__ void add_kernel() {
    size_t i = ((size_t)blockIdx.x * blockDim.x + threadIdx.x) * 4;
    if (i >= NR) return;
    float4 f = *reinterpret_cast<const float4*>(&g_FTf[i]);
    float4 u = *reinterpret_cast<const float4*>(&g_UT[i]);
    float w0 = f.x + u.x, w1 = f.y + u.y, w2 = f.z + u.z, w3 = f.w + u.w;
    __nv_bfloat16 h0, l0, h1, l1, h2, l2, h3, l3;
    split1(w0, h0, l0); split1(w1, h1, l1); split1(w2, h2, l2); split1(w3, h3, l3);
    uint2 hp, lp;
    hp.x = pack2(h0, h1); hp.y = pack2(h2, h3);
    lp.x = pack2(l0, l1); lp.y = pack2(l2, l3);
    *reinterpret_cast<uint2*>(&g_WTh[i]) = hp;
    *reinterpret_cast<uint2*>(&g_WTl[i]) = lp;
}

// ===================== host =====================
constexpr int GSM = 2 * 40960;
constexpr int GSM_H = 2 * 20480;

extern "C" void kernel_launch(void* const* d_in, const int* in_sizes, int n_in,
                              void* d_out, int out_size) {
    const float* feature = (const float*)d_in[0];
    PrepArgs pa;
    for (int L = 0; L < 5; ++L) {
        pa.W[L] = (const float*)d_in[1 + 5 * L + 0];
        pa.g[L] = (const float*)d_in[1 + 5 * L + 1];
        pa.b[L] = (const float*)d_in[1 + 5 * L + 2];
        pa.m[L] = (const float*)d_in[1 + 5 * L + 3];
        pa.v[L] = (const float*)d_in[1 + 5 * L + 4];
    }

    __nv_bfloat16 *XTh, *XTl, *FTh, *FTl, *QTh, *QTl, *KTh, *KTl;
    __nv_bfloat16 *WTh, *WTl, *Wph, *Wpl;
    __half *V16, *P16;
    float *FTf, *S, *UT, *Al, *Be;
    cudaGetSymbolAddress((void**)&XTh, g_XTh); cudaGetSymbolAddress((void**)&XTl, g_XTl);
    cudaGetSymbolAddress((void**)&FTh, g_FTh); cudaGetSymbolAddress((void**)&FTl, g_FTl);
    cudaGetSymbolAddress((void**)&QTh, g_QTh); cudaGetSymbolAddress((void**)&QTl, g_QTl);
    cudaGetSymbolAddress((void**)&KTh, g_KTh); cudaGetSymbolAddress((void**)&KTl, g_KTl);
    cudaGetSymbolAddress((void**)&V16, g_V16); cudaGetSymbolAddress((void**)&P16, g_P16);
    cudaGetSymbolAddress((void**)&WTh, g_WTh); cudaGetSymbolAddress((void**)&WTl, g_WTl);
    cudaGetSymbolAddress((void**)&Wph, g_Wph); cudaGetSymbolAddress((void**)&Wpl, g_Wpl);
    cudaGetSymbolAddress((void**)&FTf, g_FTf); cudaGetSymbolAddress((void**)&S, g_S);
    cudaGetSymbolAddress((void**)&UT, g_UT);
    cudaGetSymbolAddress((void**)&Al, g_alpha); cudaGetSymbolAddress((void**)&Be, g_beta);

    cudaFuncSetAttribute(gemm_bf16s<2, true, true, true, false>,   cudaFuncAttributeMaxDynamicSharedMemorySize, GSM);
    cudaFuncSetAttribute(gemm_bf16s<2, false, true, true, false>,  cudaFuncAttributeMaxDynamicSharedMemorySize, GSM);
    cudaFuncSetAttribute(gemm_bf16s<1, false, true, false, true>,  cudaFuncAttributeMaxDynamicSharedMemorySize, GSM);
    cudaFuncSetAttribute(gemm_bf16s<0, true, false, false, false>, cudaFuncAttributeMaxDynamicSharedMemorySize, GSM);
    cudaFuncSetAttribute(gemm_bf16s<1, true, false, false, false>, cudaFuncAttributeMaxDynamicSharedMemorySize, GSM);
    cudaFuncSetAttribute(gemm_f16, cudaFuncAttributeMaxDynamicSharedMemorySize, GSM_H);

    const long sNR = (long)Nn * Rr;
    const long sNN = (long)Nn * Nn;

    // 1) prep
    prep_kernel<<<(int)((WTOT + 4096 + 255) / 256), 256>>>(pa);

    // 2) XT = transpose+split(feature)
    xt_kernel<<<dim3(Cc / 32, Nn / 32, Bb), 256>>>(feature);

    // 3) FT = cbr-col(XT x Wr)   M=4096, N=512, K=2048
    gemm_bf16s<2, true, true, true, false><<<dim3(4, 32, Bb), 128, GSM>>>(
        XTh, XTl, Wph + WOF[0], Wpl + WOF[0], FTf, FTh, FTl,
        Cc, Rr, (long)Nn * Cc, 0, sNR, Al + 0 * 2048, Be + 0 * 2048);

    // 4) QT = cbr-col(FT x Wq)
    gemm_bf16s<2, false, true, true, false><<<dim3(4, 32, Bb), 128, GSM>>>(
        FTh, FTl, Wph + WOF[1], Wpl + WOF[1], nullptr, QTh, QTl,
        Rr, Rr, sNR, 0, sNR, Al + 1 * 2048, Be + 1 * 2048);

    // 5) KT = cbr-col(FT x Wk)
    gemm_bf16s<2, false, true, true, false><<<dim3(4, 32, Bb), 128, GSM>>>(
        FTh, FTl, Wph + WOF[2], Wpl + WOF[2], nullptr, KTh, KTl,
        Rr, Rr, sNR, 0, sNR, Al + 2 * 2048, Be + 2 * 2048);

    // 6) S = QT x KT^T   M=N=4096, K=512  (bf16 3-product, proven)
    gemm_bf16s<0, true, false, false, false><<<dim3(32, 32, Bb), 128, GSM>>>(
        QTh, QTl, KTh, KTl, S, nullptr, nullptr,
        Rr, Nn, sNR, sNR, sNN, nullptr, nullptr);

    // 7) V = cbr-row(Wv x F)   M=512, N=4096, K=512 -> fp16 plane [R][N]
    gemm_bf16s<1, false, true, false, true><<<dim3(32, 4, Bb), 128, GSM>>>(
        Wph + WOF[3], Wpl + WOF[3], FTh, FTl, nullptr,
        reinterpret_cast<__nv_bfloat16*>(V16), nullptr,
        Rr, Nn, 0, sNR, (long)Rr * Nn, Al + 3 * 2048, Be + 3 * 2048);

    // 8) P = softmax rows -> fp16 plane
    softmax_kernel<<<Bb * Nn, 256>>>();

    // 9) UT = P x V^T   fp16 single-product, M=4096, N=512, K=4096
    gemm_f16<<<dim3(4, 32, Bb), 128, GSM_H>>>(
        P16, V16, UT, Nn, Rr, sNN, (long)Rr * Nn, sNR);

    // 10) WT = split(FTf + UT)
    add_kernel<<<(int)((NR / 4 + 255) / 256), 256>>>();

    // 11) out = cbr-row(Wu x (F+U))   M=2048, N=4096, K=512
    gemm_bf16s<1, true, false, false, false><<<dim3(32, 16, Bb), 128, GSM>>>(
        Wph + WOF[4], Wpl + WOF[4], WTh, WTl, (float*)d_out, nullptr, nullptr,
        Rr, Nn, 0, sNR, (long)Cc * Nn, Al + 4 * 2048, Be + 4 * 2048);
}

// round 17
// speedup vs baseline: 1.7713x; 1.0417x over previous
#include <cuda_runtime.h>
#include <cuda_bf16.h>
#include <cuda_fp16.h>
#include <cstdint>
#include <cstddef>

#define EPS_BN 1e-5f

constexpr int Bb = 4;
constexpr int Cc = 2048;
constexpr int Rr = 512;
constexpr int Nn = 4096;   // H*W

constexpr size_t NC = (size_t)Bb * Nn * Cc;
constexpr size_t NR = (size_t)Bb * Nn * Rr;
constexpr size_t NNe = (size_t)Bb * Nn * Nn;

constexpr size_t WOF[5] = {0, 1048576, 1310720, 1572864, 1835008};
constexpr size_t WTOT = 2883584;

// ---- scratch (allocation-free) ----
__device__ __nv_bfloat16 g_XTh[NC], g_XTl[NC];
__device__ __nv_bfloat16 g_FTh[NR], g_FTl[NR];
__device__ float         g_FTf[NR];
__device__ __nv_bfloat16 g_QTh[NR], g_QTl[NR];
__device__ __nv_bfloat16 g_KTh[NR], g_KTl[NR];
__device__ __half        g_V16[NR];                 // V fp16 [B][R][N]
__device__ float         g_S[NNe];
__device__ __half        g_P16[NNe];                // softmax fp16 [B][N][N]
__device__ float         g_UT[NR];
__device__ __half        g_WT16[NR];                // (F+U)^T fp16 [B][N][R]
__device__ __nv_bfloat16 g_Wph[WTOT], g_Wpl[WTOT];  // bf16 pair planes (r,q,k,v)
__device__ __half        g_Wu16h[1048576], g_Wu16l[1048576];  // Wu fp16 pair
__device__ float g_alpha[5 * 2048], g_beta[5 * 2048];

// ===================== helpers =====================
__device__ __forceinline__ uint32_t smem_u32(const void* p) {
    uint32_t a;
    asm("{ .reg .u64 t; cvta.to.shared.u64 t, %1; cvt.u32.u64 %0, t; }" : "=r"(a) : "l"(p));
    return a;
}
__device__ __forceinline__ void ldsm4(uint32_t* r, uint32_t addr) {
    asm volatile("ldmatrix.sync.aligned.m8n8.x4.shared.b16 {%0,%1,%2,%3}, [%4];"
                 : "=r"(r[0]), "=r"(r[1]), "=r"(r[2]), "=r"(r[3]) : "r"(addr));
}
__device__ __forceinline__ void mma_bf16(float* c, const uint32_t* a, uint32_t b0, uint32_t b1) {
    asm volatile(
        "mma.sync.aligned.m16n8k16.row.col.f32.bf16.bf16.f32 "
        "{%0,%1,%2,%3}, {%4,%5,%6,%7}, {%8,%9}, {%0,%1,%2,%3};"
        : "+f"(c[0]), "+f"(c[1]), "+f"(c[2]), "+f"(c[3])
        : "r"(a[0]), "r"(a[1]), "r"(a[2]), "r"(a[3]), "r"(b0), "r"(b1));
}
__device__ __forceinline__ void mma_f16(float* c, const uint32_t* a, uint32_t b0, uint32_t b1) {
    asm volatile(
        "mma.sync.aligned.m16n8k16.row.col.f32.f16.f16.f32 "
        "{%0,%1,%2,%3}, {%4,%5,%6,%7}, {%8,%9}, {%0,%1,%2,%3};"
        : "+f"(c[0]), "+f"(c[1]), "+f"(c[2]), "+f"(c[3])
        : "r"(a[0]), "r"(a[1]), "r"(a[2]), "r"(a[3]), "r"(b0), "r"(b1));
}
__device__ __forceinline__ void cp16(uint32_t s, const void* g) {
    asm volatile("cp.async.cg.shared.global [%0], [%1], 16;" :: "r"(s), "l"(g));
}
__device__ __forceinline__ void cp_commit() {
    asm volatile("cp.async.commit_group;" ::: "memory");
}
__device__ __forceinline__ void cp_wait0() {
    asm volatile("cp.async.wait_group 0;" ::: "memory");
}
__device__ __forceinline__ void split1(float x, __nv_bfloat16& h, __nv_bfloat16& l) {
    h = __float2bfloat16_rn(x);
    l = __float2bfloat16_rn(x - __bfloat162float(h));
}
__device__ __forceinline__ uint32_t pack2(__nv_bfloat16 a, __nv_bfloat16 b) {
    __nv_bfloat162 p; p.x = a; p.y = b;
    return *reinterpret_cast<uint32_t*>(&p);
}
__device__ __forceinline__ uint32_t pack2h(float a, float b) {
    __half2 p = __floats2half2_rn(a, b);
    return *reinterpret_cast<uint32_t*>(&p);
}

// ===================== prep =====================
struct PrepArgs {
    const float* W[5];
    const float* g[5];
    const float* b[5];
    const float* m[5];
    const float* v[5];
};

__global__ void prep_kernel(PrepArgs a) {
    const size_t wof[5] = {0, 1048576, 1310720, 1572864, 1835008};
    const int wsz[5] = {1048576, 262144, 262144, 262144, 1048576};
    int id = blockIdx.x * blockDim.x + threadIdx.x;
    if (id < 4096) {
        int L, i;
        if (id < 2048) { L = id >> 9; i = id & 511; }
        else { L = 4; i = id - 2048; }
        float al = a.g[L][i] * rsqrtf(a.v[L][i] + EPS_BN);
        g_alpha[L * 2048 + i] = al;
        g_beta[L * 2048 + i] = a.b[L][i] - a.m[L][i] * al;
        return;
    }
    size_t w = (size_t)id - 4096;
    if (w >= WTOT) return;
    int L = 0;
    size_t off = w;
    while (L < 4 && off >= (size_t)wsz[L]) { off -= wsz[L]; ++L; }
    float x = a.W[L][off];
    if (L == 4) {
        __half h = __float2half_rn(x);
        __half l = __float2half_rn(x - __half2float(h));
        g_Wu16h[off] = h;
        g_Wu16l[off] = l;
    } else {
        split1(x, g_Wph[wof[L] + off], g_Wpl[wof[L] + off]);
    }
}

// ===================== feature transpose + split ============================
__global__ __launch_bounds__(256) void xt_kernel(const float* __restrict__ X) {
    __shared__ float s[32][33];
    const int c0 = blockIdx.x * 32;
    const int n0 = blockIdx.y * 32;
    const size_t zo = (size_t)blockIdx.z * Cc * Nn;
    const int tx = threadIdx.x & 31;
    const int ty = threadIdx.x >> 5;
#pragma unroll
    for (int i = 0; i < 4; ++i)
        s[ty + 8 * i][tx] = X[zo + (size_t)(c0 + ty + 8 * i) * Nn + n0 + tx];
    __syncthreads();
    const size_t zo2 = (size_t)blockIdx.z * Nn * Cc;
#pragma unroll
    for (int i = 0; i < 4; ++i) {
        float val = s[tx][ty + 8 * i];
        size_t o = zo2 + (size_t)(n0 + ty + 8 * i) * Cc + c0 + tx;
        split1(val, g_XTh[o], g_XTl[o]);
    }
}

// ===================== canonical split-bf16 GEMM (R8 form) ==================
// C[i,j] = sum_k A[i,k]*B[j,k];  A planes [M][K], B planes [N][K] (K contig).
// SCALE: 0 none, 1 row alpha[i], 2 col alpha[j]; >0 implies ReLU.
// OPL: write plane output; H16: plane output is fp16 single plane (Ch only).
template <int SCALE, bool OF32, bool OPL, bool WLO, bool H16>
__global__ __launch_bounds__(128, 2) void gemm_bf16s(
    const __nv_bfloat16* __restrict__ Ah, const __nv_bfloat16* __restrict__ Al,
    const __nv_bfloat16* __restrict__ Bh, const __nv_bfloat16* __restrict__ Bl,
    float* __restrict__ Cf, __nv_bfloat16* __restrict__ Ch, __nv_bfloat16* __restrict__ Cl,
    int K, int ldc, long sA, long sB, long sC,
    const float* __restrict__ alpha, const float* __restrict__ beta) {
    extern __shared__ __align__(16) char smem[];
    const uint32_t su = smem_u32(smem);

    constexpr int STGB = 40960;
    constexpr int BOFF = 20480;

    const int t = threadIdx.x;
    const int lane = t & 31;
    const int wid = t >> 5;
    const int warp_m = wid >> 1;
    const int warp_n = wid & 1;
    const int bi = blockIdx.y * 128;
    const int bj = blockIdx.x * 128;
    const size_t zA = (size_t)sA * blockIdx.z;
    const size_t zB = (size_t)sB * blockIdx.z;
    const size_t zC = (size_t)sC * blockIdx.z;

    const int row = t >> 2;
    const int kc = t & 3;

    auto load_stage = [&](int stage, int k0) {
        const uint32_t sb = su + stage * STGB;
#pragma unroll
        for (int i = 0; i < 4; ++i) {
            int r = row + 32 * i;
            uint32_t so = r * 80 + kc * 16;
            cp16(sb + so,         (const char*)(Ah + zA + (size_t)(bi + r) * K + k0) + kc * 16);
            cp16(sb + 10240 + so, (const char*)(Al + zA + (size_t)(bi + r) * K + k0) + kc * 16);
            cp16(sb + BOFF + so,  (const char*)(Bh + zB + (size_t)(bj + r) * K + k0) + kc * 16);
            cp16(sb + 30720 + so, (const char*)(Bl + zB + (size_t)(bj + r) * K + k0) + kc * 16);
        }
        cp_commit();
    };

    float acc[4][8][4] = {};
    const int T = K / 32;

    load_stage(0, 0);

    const uint32_t aoff = (uint32_t)((warp_m * 64 + (lane & 15)) * 80 + (lane >> 4) * 16);
    const uint32_t boff = (uint32_t)(BOFF + (warp_n * 64 + (lane & 15)) * 80 + (lane >> 4) * 16);

    for (int tt = 0; tt < T; ++tt) {
        cp_wait0();
        __syncthreads();
        if (tt + 1 < T) load_stage((tt + 1) & 1, (tt + 1) * 32);

        const uint32_t sb = su + (tt & 1) * STGB;
        const uint32_t aHi = sb + aoff, aLo = aHi + 10240;
        const uint32_t bHi = sb + boff, bLo = bHi + 10240;

#pragma unroll
        for (int ks = 0; ks < 2; ++ks) {
            const uint32_t kof = (uint32_t)(ks * 32);
            uint32_t bh[4][4], bl[4][4];
#pragma unroll
            for (int np = 0; np < 4; ++np) {
                ldsm4(bh[np], bHi + (uint32_t)(np * 16 * 80) + kof);
                ldsm4(bl[np], bLo + (uint32_t)(np * 16 * 80) + kof);
            }
#pragma unroll
            for (int mt = 0; mt < 4; ++mt) {
                uint32_t ah[4], al_[4];
                ldsm4(ah, aHi + (uint32_t)(mt * 16 * 80) + kof);
                ldsm4(al_, aLo + (uint32_t)(mt * 16 * 80) + kof);
#pragma unroll
                for (int nt = 0; nt < 8; ++nt) {
                    const uint32_t* h = bh[nt >> 1];
                    const uint32_t* l = bl[nt >> 1];
                    mma_bf16(acc[mt][nt], ah, h[nt & 1], h[2 + (nt & 1)]);
                    mma_bf16(acc[mt][nt], al_, h[nt & 1], h[2 + (nt & 1)]);
                    mma_bf16(acc[mt][nt], ah, l[nt & 1], l[2 + (nt & 1)]);
                }
            }
        }
    }

#pragma unroll
    for (int mt = 0; mt < 4; ++mt) {
        const int m0 = bi + warp_m * 64 + mt * 16 + (lane >> 2);
        float ra0 = 1.f, rb0 = 0.f, ra1 = 1.f, rb1 = 0.f;
        if (SCALE == 1) {
            ra0 = alpha[m0]; rb0 = beta[m0];
            ra1 = alpha[m0 + 8]; rb1 = beta[m0 + 8];
        }
#pragma unroll
        for (int nt = 0; nt < 8; ++nt) {
            const int n = bj + warp_n * 64 + nt * 8 + (lane & 3) * 2;
            float v0 = acc[mt][nt][0], v1 = acc[mt][nt][1];
            float v2 = acc[mt][nt][2], v3 = acc[mt][nt][3];
            if (SCALE == 1) {
                v0 = fmaxf(fmaf(ra0, v0, rb0), 0.f); v1 = fmaxf(fmaf(ra0, v1, rb0), 0.f);
                v2 = fmaxf(fmaf(ra1, v2, rb1), 0.f); v3 = fmaxf(fmaf(ra1, v3, rb1), 0.f);
            } else if (SCALE == 2) {
                float ca0 = alpha[n], cb0 = beta[n], ca1 = alpha[n + 1], cb1 = beta[n + 1];
                v0 = fmaxf(fmaf(ca0, v0, cb0), 0.f); v1 = fmaxf(fmaf(ca1, v1, cb1), 0.f);
                v2 = fmaxf(fmaf(ca0, v2, cb0), 0.f); v3 = fmaxf(fmaf(ca1, v3, cb1), 0.f);
            }
            if (OF32) {
                *reinterpret_cast<float2*>(&Cf[zC + (size_t)m0 * ldc + n]) = make_float2(v0, v1);
                *reinterpret_cast<float2*>(&Cf[zC + (size_t)(m0 + 8) * ldc + n]) = make_float2(v2, v3);
            }
            if (OPL) {
                if (H16) {
                    *reinterpret_cast<uint32_t*>(&Ch[zC + (size_t)m0 * ldc + n]) = pack2h(v0, v1);
                    *reinterpret_cast<uint32_t*>(&Ch[zC + (size_t)(m0 + 8) * ldc + n]) = pack2h(v2, v3);
                } else {
                    __nv_bfloat16 h0, l0, h1, l1;
                    split1(v0, h0, l0); split1(v1, h1, l1);
                    *reinterpret_cast<uint32_t*>(&Ch[zC + (size_t)m0 * ldc + n]) = pack2(h0, h1);
                    if (WLO) *reinterpret_cast<uint32_t*>(&Cl[zC + (size_t)m0 * ldc + n]) = pack2(l0, l1);
                    split1(v2, h0, l0); split1(v3, h1, l1);
                    *reinterpret_cast<uint32_t*>(&Ch[zC + (size_t)(m0 + 8) * ldc + n]) = pack2(h0, h1);
                    if (WLO) *reinterpret_cast<uint32_t*>(&Cl[zC + (size_t)(m0 + 8) * ldc + n]) = pack2(l0, l1);
                }
            }
        }
    }
}

// ===================== single-product fp16 GEMM (U = P x V^T) ===============
__global__ __launch_bounds__(128, 2) void gemm_f16(
    const __half* __restrict__ A, const __half* __restrict__ B,
    float* __restrict__ Cf,
    int K, int ldc, long sA, long sB, long sC) {
    extern __shared__ __align__(16) char smem[];
    const uint32_t su = smem_u32(smem);

    constexpr int STGB = 20480;
    constexpr int BOFF = 10240;

    const int t = threadIdx.x;
    const int lane = t & 31;
    const int wid = t >> 5;
    const int warp_m = wid >> 1;
    const int warp_n = wid & 1;
    const int bi = blockIdx.y * 128;
    const int bj = blockIdx.x * 128;
    const size_t zA = (size_t)sA * blockIdx.z;
    const size_t zB = (size_t)sB * blockIdx.z;
    const size_t zC = (size_t)sC * blockIdx.z;

    const int row = t >> 2;
    const int kc = t & 3;

    auto load_stage = [&](int stage, int k0) {
        const uint32_t sb = su + stage * STGB;
#pragma unroll
        for (int i = 0; i < 4; ++i) {
            int r = row + 32 * i;
            uint32_t so = r * 80 + kc * 16;
            cp16(sb + so,        (const char*)(A + zA + (size_t)(bi + r) * K + k0) + kc * 16);
            cp16(sb + BOFF + so, (const char*)(B + zB + (size_t)(bj + r) * K + k0) + kc * 16);
        }
        cp_commit();
    };

    float acc[4][8][4] = {};
    const int T = K / 32;

    load_stage(0, 0);

    const uint32_t aoff = (uint32_t)((warp_m * 64 + (lane & 15)) * 80 + (lane >> 4) * 16);
    const uint32_t boff = (uint32_t)(BOFF + (warp_n * 64 + (lane & 15)) * 80 + (lane >> 4) * 16);

    for (int tt = 0; tt < T; ++tt) {
        cp_wait0();
        __syncthreads();
        if (tt + 1 < T) load_stage((tt + 1) & 1, (tt + 1) * 32);

        const uint32_t sb = su + (tt & 1) * STGB;
        const uint32_t aBase = sb + aoff;
        const uint32_t bBase = sb + boff;

#pragma unroll
        for (int ks = 0; ks < 2; ++ks) {
            const uint32_t kof = (uint32_t)(ks * 32);
            uint32_t bh[4][4];
#pragma unroll
            for (int np = 0; np < 4; ++np)
                ldsm4(bh[np], bBase + (uint32_t)(np * 16 * 80) + kof);
#pragma unroll
            for (int mt = 0; mt < 4; ++mt) {
                uint32_t ah[4];
                ldsm4(ah, aBase + (uint32_t)(mt * 16 * 80) + kof);
#pragma unroll
                for (int nt = 0; nt < 8; ++nt) {
                    const uint32_t* h = bh[nt >> 1];
                    mma_f16(acc[mt][nt], ah, h[nt & 1], h[2 + (nt & 1)]);
                }
            }
        }
    }

#pragma unroll
    for (int mt = 0; mt < 4; ++mt) {
        const int m0 = bi + warp_m * 64 + mt * 16 + (lane >> 2);
#pragma unroll
        for (int nt = 0; nt < 8; ++nt) {
            const int n = bj + warp_n * 64 + nt * 8 + (lane & 3) * 2;
            *reinterpret_cast<float2*>(&Cf[zC + (size_t)m0 * ldc + n]) =
                make_float2(acc[mt][nt][0], acc[mt][nt][1]);
            *reinterpret_cast<float2*>(&Cf[zC + (size_t)(m0 + 8) * ldc + n]) =
                make_float2(acc[mt][nt][2], acc[mt][nt][3]);
        }
    }
}

// ===================== fp16 pair x single GEMM (out = Wu x WT) ==============
// C[i,j] = sum_k (Ah+Al)[i,k]*B[j,k]; A weights (no batch), B fp16 [N][K].
// 2 MMAs per fragment pair. Row scale+bias+ReLU epilogue, fp32 out.
__global__ __launch_bounds__(128, 2) void gemm_f16p(
    const __half* __restrict__ Ah, const __half* __restrict__ Al,
    const __half* __restrict__ B, float* __restrict__ Cf,
    int K, int ldc, long sB, long sC,
    const float* __restrict__ alpha, const float* __restrict__ beta) {
    extern __shared__ __align__(16) char smem[];
    const uint32_t su = smem_u32(smem);

    constexpr int STGB = 30720;     // Ah,Al,B @ 10240 each
    constexpr int BOFF = 20480;

    const int t = threadIdx.x;
    const int lane = t & 31;
    const int wid = t >> 5;
    const int warp_m = wid >> 1;
    const int warp_n = wid & 1;
    const int bi = blockIdx.y * 128;
    const int bj = blockIdx.x * 128;
    const size_t zB = (size_t)sB * blockIdx.z;
    const size_t zC = (size_t)sC * blockIdx.z;

    const int row = t >> 2;
    const int kc = t & 3;

    auto load_stage = [&](int stage, int k0) {
        const uint32_t sb = su + stage * STGB;
#pragma unroll
        for (int i = 0; i < 4; ++i) {
            int r = row + 32 * i;
            uint32_t so = r * 80 + kc * 16;
            cp16(sb + so,         (const char*)(Ah + (size_t)(bi + r) * K + k0) + kc * 16);
            cp16(sb + 10240 + so, (const char*)(Al + (size_t)(bi + r) * K + k0) + kc * 16);
            cp16(sb + BOFF + so,  (const char*)(B + zB + (size_t)(bj + r) * K + k0) + kc * 16);
        }
        cp_commit();
    };

    float acc[4][8][4] = {};
    const int T = K / 32;

    load_stage(0, 0);

    const uint32_t aoff = (uint32_t)((warp_m * 64 + (lane & 15)) * 80 + (lane >> 4) * 16);
    const uint32_t boff = (uint32_t)(BOFF + (warp_n * 64 + (lane & 15)) * 80 + (lane >> 4) * 16);

    for (int tt = 0; tt < T; ++tt) {
        cp_wait0();
        __syncthreads();
        if (tt + 1 < T) load_stage((tt + 1) & 1, (tt + 1) * 32);

        const uint32_t sb = su + (tt & 1) * STGB;
        const uint32_t aHi = sb + aoff, aLo = aHi + 10240;
        const uint32_t bBase = sb + boff;

#pragma unroll
        for (int ks = 0; ks < 2; ++ks) {
            const uint32_t kof = (uint32_t)(ks * 32);
            uint32_t bh[4][4];
#pragma unroll
            for (int np = 0; np < 4; ++np)
                ldsm4(bh[np], bBase + (uint32_t)(np * 16 * 80) + kof);
#pragma unroll
            for (int mt = 0; mt < 4; ++mt) {
                uint32_t ah[4], al_[4];
                ldsm4(ah, aHi + (uint32_t)(mt * 16 * 80) + kof);
                ldsm4(al_, aLo + (uint32_t)(mt * 16 * 80) + kof);
#pragma unroll
                for (int nt = 0; nt < 8; ++nt) {
                    const uint32_t* h = bh[nt >> 1];
                    mma_f16(acc[mt][nt], ah, h[nt & 1], h[2 + (nt & 1)]);
                    mma_f16(acc[mt][nt], al_, h[nt & 1], h[2 + (nt & 1)]);
                }
            }
        }
    }

#pragma unroll
    for (int mt = 0; mt < 4; ++mt) {
        const int m0 = bi + warp_m * 64 + mt * 16 + (lane >> 2);
        const float ra0 = alpha[m0], rb0 = beta[m0];
        const float ra1 = alpha[m0 + 8], rb1 = beta[m0 + 8];
#pragma unroll
        for (int nt = 0; nt < 8; ++nt) {
            const int n = bj + warp_n * 64 + nt * 8 + (lane & 3) * 2;
            float v0 = fmaxf(fmaf(ra0, acc[mt][nt][0], rb0), 0.f);
            float v1 = fmaxf(fmaf(ra0, acc[mt][nt][1], rb0), 0.f);
            float v2 = fmaxf(fmaf(ra1, acc[mt][nt][2], rb1), 0.f);
            float v3 = fmaxf(fmaf(ra1, acc[mt][nt][3], rb1), 0.f);
            *reinterpret_cast<float2*>(&Cf[zC + (size_t)m0 * ldc + n]) = make_float2(v0, v1);
            *reinterpret_cast<float2*>(&Cf[zC + (size_t)(m0 + 8) * ldc + n]) = make_float2(v2, v3);
        }
    }
}

// ===================== softmax -> fp16 plane ================================
__global__ __launch_bounds__(256) void softmax_kernel() {
    const size_t ro = (size_t)blockIdx.x * Nn;
    const float* row = g_S + ro;
    const int t = threadIdx.x;
    __shared__ float redm[8], reds[8];

    float v[16];
    float m = -1e30f;
#pragma unroll
    for (int u = 0; u < 16; ++u) {
        v[u] = row[t + u * 256];
        m = fmaxf(m, v[u]);
    }
#pragma unroll
    for (int o = 16; o; o >>= 1) m = fmaxf(m, __shfl_xor_sync(0xffffffffu, m, o));
    if ((t & 31) == 0) redm[t >> 5] = m;
    __syncthreads();
    m = redm[0];
#pragma unroll
    for (int w = 1; w < 8; ++w) m = fmaxf(m, redm[w]);

    float s = 0.f;
#pragma unroll
    for (int u = 0; u < 16; ++u) {
        v[u] = __expf(v[u] - m);
        s += v[u];
    }
#pragma unroll
    for (int o = 16; o; o >>= 1) s += __shfl_xor_sync(0xffffffffu, s, o);
    if ((t & 31) == 0) reds[t >> 5] = s;
    __syncthreads();
    float tot = 0.f;
#pragma unroll
    for (int w = 0; w < 8; ++w) tot += reds[w];
    float inv = 1.0f / tot;
#pragma unroll
    for (int u = 0; u < 16; ++u)
        g_P16[ro + t + u * 256] = __float2half_rn(v[u] * inv);
}

// ===================== add -> fp16 plane ====================================
__global__ void add_kernel() {
    size_t i = ((size_t)blockIdx.x * blockDim.x + threadIdx.x) * 4;
    if (i >= NR) return;
    float4 f = *reinterpret_cast<const float4*>(&g_FTf[i]);
    float4 u = *reinterpret_cast<const float4*>(&g_UT[i]);
    uint2 o;
    o.x = pack2h(f.x + u.x, f.y + u.y);
    o.y = pack2h(f.z + u.z, f.w + u.w);
    *reinterpret_cast<uint2*>(&g_WT16[i]) = o;
}

// ===================== host =====================
constexpr int GSM = 2 * 40960;
constexpr int GSM_H = 2 * 20480;
constexpr int GSM_P = 2 * 30720;

extern "C" void kernel_launch(void* const* d_in, const int* in_sizes, int n_in,
                              void* d_out, int out_size) {
    const float* feature = (const float*)d_in[0];
    PrepArgs pa;
    for (int L = 0; L < 5; ++L) {
        pa.W[L] = (const float*)d_in[1 + 5 * L + 0];
        pa.g[L] = (const float*)d_in[1 + 5 * L + 1];
        pa.b[L] = (const float*)d_in[1 + 5 * L + 2];
        pa.m[L] = (const float*)d_in[1 + 5 * L + 3];
        pa.v[L] = (const float*)d_in[1 + 5 * L + 4];
    }

    __nv_bfloat16 *XTh, *XTl, *FTh, *FTl, *QTh, *QTl, *KTh, *KTl, *Wph, *Wpl;
    __half *V16, *P16, *WT16, *Wu16h, *Wu16l;
    float *FTf, *S, *UT, *Al, *Be;
    cudaGetSymbolAddress((void**)&XTh, g_XTh); cudaGetSymbolAddress((void**)&XTl, g_XTl);
    cudaGetSymbolAddress((void**)&FTh, g_FTh); cudaGetSymbolAddress((void**)&FTl, g_FTl);
    cudaGetSymbolAddress((void**)&QTh, g_QTh); cudaGetSymbolAddress((void**)&QTl, g_QTl);
    cudaGetSymbolAddress((void**)&KTh, g_KTh); cudaGetSymbolAddress((void**)&KTl, g_KTl);
    cudaGetSymbolAddress((void**)&V16, g_V16); cudaGetSymbolAddress((void**)&P16, g_P16);
    cudaGetSymbolAddress((void**)&WT16, g_WT16);
    cudaGetSymbolAddress((void**)&Wu16h, g_Wu16h); cudaGetSymbolAddress((void**)&Wu16l, g_Wu16l);
    cudaGetSymbolAddress((void**)&Wph, g_Wph); cudaGetSymbolAddress((void**)&Wpl, g_Wpl);
    cudaGetSymbolAddress((void**)&FTf, g_FTf); cudaGetSymbolAddress((void**)&S, g_S);
    cudaGetSymbolAddress((void**)&UT, g_UT);
    cudaGetSymbolAddress((void**)&Al, g_alpha); cudaGetSymbolAddress((void**)&Be, g_beta);

    cudaFuncSetAttribute(gemm_bf16s<2, true, true, true, false>,   cudaFuncAttributeMaxDynamicSharedMemorySize, GSM);
    cudaFuncSetAttribute(gemm_bf16s<2, false, true, true, false>,  cudaFuncAttributeMaxDynamicSharedMemorySize, GSM);
    cudaFuncSetAttribute(gemm_bf16s<1, false, true, false, true>,  cudaFuncAttributeMaxDynamicSharedMemorySize, GSM);
    cudaFuncSetAttribute(gemm_bf16s<0, true, false, false, false>, cudaFuncAttributeMaxDynamicSharedMemorySize, GSM);
    cudaFuncSetAttribute(gemm_f16,  cudaFuncAttributeMaxDynamicSharedMemorySize, GSM_H);
    cudaFuncSetAttribute(gemm_f16p, cudaFuncAttributeMaxDynamicSharedMemorySize, GSM_P);

    const long sNR = (long)Nn * Rr;
    const long sNN = (long)Nn * Nn;

    // 1) prep
    prep_kernel<<<(int)((WTOT + 4096 + 255) / 256), 256>>>(pa);

    // 2) XT = transpose+split(feature)
    xt_kernel<<<dim3(Cc / 32, Nn / 32, Bb), 256>>>(feature);

    // 3) FT = cbr-col(XT x Wr)   M=4096, N=512, K=2048
    gemm_bf16s<2, true, true, true, false><<<dim3(4, 32, Bb), 128, GSM>>>(
        XTh, XTl, Wph + WOF[0], Wpl + WOF[0], FTf, FTh, FTl,
        Cc, Rr, (long)Nn * Cc, 0, sNR, Al + 0 * 2048, Be + 0 * 2048);

    // 4) QT = cbr-col(FT x Wq)
    gemm_bf16s<2, false, true, true, false><<<dim3(4, 32, Bb), 128, GSM>>>(
        FTh, FTl, Wph + WOF[1], Wpl + WOF[1], nullptr, QTh, QTl,
        Rr, Rr, sNR, 0, sNR, Al + 1 * 2048, Be + 1 * 2048);

    // 5) KT = cbr-col(FT x Wk)
    gemm_bf16s<2, false, true, true, false><<<dim3(4, 32, Bb), 128, GSM>>>(
        FTh, FTl, Wph + WOF[2], Wpl + WOF[2], nullptr, KTh, KTl,
        Rr, Rr, sNR, 0, sNR, Al + 2 * 2048, Be + 2 * 2048);

    // 6) S = QT x KT^T   M=N=4096, K=512  (bf16 3-product, proven)
    gemm_bf16s<0, true, false, false, false><<<dim3(32, 32, Bb), 128, GSM>>>(
        QTh, QTl, KTh, KTl, S, nullptr, nullptr,
        Rr, Nn, sNR, sNR, sNN, nullptr, nullptr);

    // 7) V = cbr-row(Wv x F)   M=512, N=4096, K=512 -> fp16 plane [R][N]
    gemm_bf16s<1, false, true, false, true><<<dim3(32, 4, Bb), 128, GSM>>>(
        Wph + WOF[3], Wpl + WOF[3], FTh, FTl, nullptr,
        reinterpret_cast<__nv_bfloat16*>(V16), nullptr,
        Rr, Nn, 0, sNR, (long)Rr * Nn, Al + 3 * 2048, Be + 3 * 2048);

    // 8) P = softmax rows -> fp16 plane
    softmax_kernel<<<Bb * Nn, 256>>>();

    // 9) UT = P x V^T   fp16 single-product, M=4096, N=512, K=4096
    gemm_f16<<<dim3(4, 32, Bb), 128, GSM_H>>>(
        P16, V16, UT, Nn, Rr, sNN, (long)Rr * Nn, sNR);

    // 10) WT16 = fp16(FTf + UT)
    add_kernel<<<(int)((NR / 4 + 255) / 256), 256>>>();

    // 11) out = cbr-row((Wu_h+Wu_l) x WT16)   fp16 2-product, M=2048, K=512
    gemm_f16p<<<dim3(32, 16, Bb), 128, GSM_P>>>(
        Wu16h, Wu16l, WT16, (float*)d_out,
        Rr, Nn, sNR, (long)Cc * Nn, Al + 4 * 2048, Be + 4 * 2048);
}